// round 1
// baseline (speedup 1.0000x reference)
#include <cuda_runtime.h>
#include <math.h>

// Shapes
#define BB 8
#define TT 1024
#define CC 768
#define NH 12
#define NKV 4
#define HD 64
#define REP 3

// Scratch (no allocations allowed)
__device__ float g_Q[BB * TT * CC];        // [b*T+t][h*64+d]
__device__ float g_K[BB * TT * NKV * HD];  // [b*T+t][kvh*64+d]
__device__ float g_V[BB * TT * NKV * HD];
__device__ float g_A[BB * TT * CC];        // attention output, [b*T+t][h*64+d]

// ---------------------------------------------------------------------------
// Tiled SGEMM: C[M,N] = A[M,K] @ W[K,N] + bias[N]
// 64x64 block tile, 256 threads, 4x4 per thread, K-tile = 16.
// ---------------------------------------------------------------------------
__global__ void sgemm64(const float* __restrict__ A, const float* __restrict__ W,
                        const float* __restrict__ bias, float* __restrict__ C,
                        int M, int N, int K) {
    __shared__ float As[16 * 68];  // [k][m], padded stride 68
    __shared__ float Bs[16 * 64];  // [k][n]

    const int tid = threadIdx.x;
    const int tx = tid & 15;
    const int ty = tid >> 4;
    const int m0 = blockIdx.y * 64;
    const int n0 = blockIdx.x * 64;

    float acc[4][4] = {};

    for (int kt = 0; kt < K; kt += 16) {
#pragma unroll
        for (int r = 0; r < 4; r++) {
            int idx = tid + r * 256;          // 0..1023
            int m = idx >> 4, k = idx & 15;
            As[k * 68 + m] = A[(size_t)(m0 + m) * K + kt + k];
        }
#pragma unroll
        for (int r = 0; r < 4; r++) {
            int idx = tid + r * 256;
            int k = idx >> 6, n = idx & 63;
            Bs[k * 64 + n] = W[(size_t)(kt + k) * N + n0 + n];
        }
        __syncthreads();

#pragma unroll
        for (int kk = 0; kk < 16; kk++) {
            float4 a4 = *(const float4*)&As[kk * 68 + ty * 4];
            float4 b4 = *(const float4*)&Bs[kk * 64 + tx * 4];
            acc[0][0] += a4.x * b4.x; acc[0][1] += a4.x * b4.y;
            acc[0][2] += a4.x * b4.z; acc[0][3] += a4.x * b4.w;
            acc[1][0] += a4.y * b4.x; acc[1][1] += a4.y * b4.y;
            acc[1][2] += a4.y * b4.z; acc[1][3] += a4.y * b4.w;
            acc[2][0] += a4.z * b4.x; acc[2][1] += a4.z * b4.y;
            acc[2][2] += a4.z * b4.z; acc[2][3] += a4.z * b4.w;
            acc[3][0] += a4.w * b4.x; acc[3][1] += a4.w * b4.y;
            acc[3][2] += a4.w * b4.z; acc[3][3] += a4.w * b4.w;
        }
        __syncthreads();
    }

    float4 bv = *(const float4*)&bias[n0 + tx * 4];
#pragma unroll
    for (int i = 0; i < 4; i++) {
        float4 o;
        o.x = acc[i][0] + bv.x;
        o.y = acc[i][1] + bv.y;
        o.z = acc[i][2] + bv.z;
        o.w = acc[i][3] + bv.w;
        *(float4*)&C[(size_t)(m0 + ty * 4 + i) * N + n0 + tx * 4] = o;
    }
}

// ---------------------------------------------------------------------------
// RoPE (torch-style interleaved rotate_half), in place.
// buf layout: [(b*T+t)][h*64 + d], nHeads heads. One warp per head-vector.
// xh[2i] = x[i], xh[2i+1] = x[32+i]; rot = cat(-xh[32:64], xh[0:32])
// out[j] = x[j]*cos(theta_{j%32}) + rot[j]*sin(theta_{j%32})
// ---------------------------------------------------------------------------
__global__ void rope_kernel(float* __restrict__ buf, const int* __restrict__ pos,
                            int nHeads, int total) {
    __shared__ float sv[8][64];
    const int warp = threadIdx.x >> 5;
    const int lane = threadIdx.x & 31;
    const int vec = blockIdx.x * 8 + warp;
    if (vec >= total) return;

    const int h = vec % nHeads;
    const int bt = vec / nHeads;
    const int t = bt % TT;
    float* p = buf + (size_t)bt * (nHeads * HD) + h * HD;

    sv[warp][lane] = p[lane];
    sv[warp][lane + 32] = p[lane + 32];
    __syncwarp();

    const float po = (float)pos[t];
    // inv_freq[j] = 10000^{-j/32}
    const float freq = exp2f(-(float)lane * (13.287712379549449f / 32.0f));
    float sn, cs;
    sincosf(po * freq, &sn, &cs);

    const int j = lane;
    const float xj = sv[warp][j];
    const float xj32 = sv[warp][j + 32];
    // rot[j]   = -x2[j]   = -( j even ? x[16+j/2] : x[47+(j+1)/2] )
    // rot[j+32] =  x1[j]  =  ( j even ? x[j/2]    : x[32+(j-1)/2] )
    const float rot_lo = (j & 1) ? -sv[warp][47 + ((j + 1) >> 1)]
                                 : -sv[warp][16 + (j >> 1)];
    const float rot_hi = (j & 1) ? sv[warp][32 + ((j - 1) >> 1)]
                                 : sv[warp][j >> 1];
    const float o_lo = xj * cs + rot_lo * sn;
    const float o_hi = xj32 * cs + rot_hi * sn;
    p[j] = o_lo;
    p[j + 32] = o_hi;
}

// ---------------------------------------------------------------------------
// Flash attention: one block = (batch b, head h, 64-query tile).
// 256 threads (16x16), 4x4 per thread. Online softmax. Causal tile skip.
// Dynamic smem: Qs[64][68] ([qr][d]), Ks[64][68] ([d][kc] transposed),
//               Vs[64][68] ([kc][d]), Ss[64][68] ([qr][kc]), m/l/corr[64].
// ---------------------------------------------------------------------------
#define PAD 68
__global__ void attn_kernel() {
    extern __shared__ float sm[];
    float* Qs = sm;                  // 64*68
    float* Ks = Qs + 64 * PAD;       // 64*68  (transposed: [d][kc])
    float* Vs = Ks + 64 * PAD;       // 64*68  ([kc][d])
    float* Ss = Vs + 64 * PAD;       // 64*68  ([qr][kc])
    float* mrow = Ss + 64 * PAD;     // 64
    float* lrow = mrow + 64;         // 64
    float* crow = lrow + 64;         // 64

    const int tid = threadIdx.x;
    const int tx = tid & 15;
    const int ty = tid >> 4;
    const int q0 = blockIdx.x * 64;
    const int h = blockIdx.y;
    const int b = blockIdx.z;
    const int kvh = h / REP;

    const float* Qg = g_Q + (size_t)b * TT * CC + h * HD;
    const float* Kg = g_K + (size_t)b * TT * (NKV * HD) + kvh * HD;
    const float* Vg = g_V + (size_t)b * TT * (NKV * HD) + kvh * HD;

    // Load Q tile: [qr][d], coalesced, conflict-free STS
#pragma unroll
    for (int r = 0; r < 16; r++) {
        int idx = tid + r * 256;  // 0..4095
        int qr = idx >> 6, d = idx & 63;
        Qs[qr * PAD + d] = Qg[(size_t)(q0 + qr) * CC + d];
    }
    if (tid < 64) { mrow[tid] = -1e30f; lrow[tid] = 0.0f; }
    __syncthreads();

    float o[4][4] = {};

    for (int j0 = 0; j0 <= q0; j0 += 64) {
        // Load K (transposed into [d][kc]) and V ([kc][d])
#pragma unroll
        for (int r = 0; r < 16; r++) {
            int idx = tid + r * 256;
            int kc = idx >> 6, d = idx & 63;
            size_t goff = (size_t)(j0 + kc) * (NKV * HD) + d;
            Ks[d * PAD + kc] = Kg[goff];
            Vs[kc * PAD + d] = Vg[goff];
        }
        __syncthreads();

        // Scores: S[qr][kc] = Q . K
        float acc[4][4] = {};
#pragma unroll 8
        for (int d = 0; d < 64; d++) {
            float q0v = Qs[(ty * 4 + 0) * PAD + d];
            float q1v = Qs[(ty * 4 + 1) * PAD + d];
            float q2v = Qs[(ty * 4 + 2) * PAD + d];
            float q3v = Qs[(ty * 4 + 3) * PAD + d];
            float4 k4 = *(const float4*)&Ks[d * PAD + tx * 4];
            acc[0][0] += q0v * k4.x; acc[0][1] += q0v * k4.y;
            acc[0][2] += q0v * k4.z; acc[0][3] += q0v * k4.w;
            acc[1][0] += q1v * k4.x; acc[1][1] += q1v * k4.y;
            acc[1][2] += q1v * k4.z; acc[1][3] += q1v * k4.w;
            acc[2][0] += q2v * k4.x; acc[2][1] += q2v * k4.y;
            acc[2][2] += q2v * k4.z; acc[2][3] += q2v * k4.w;
            acc[3][0] += q3v * k4.x; acc[3][1] += q3v * k4.y;
            acc[3][2] += q3v * k4.z; acc[3][3] += q3v * k4.w;
        }
        const bool diag = (j0 == q0);
#pragma unroll
        for (int i = 0; i < 4; i++) {
#pragma unroll
            for (int j = 0; j < 4; j++) {
                float s = acc[i][j] * 0.125f;  // 1/sqrt(64)
                if (diag && (tx * 4 + j) > (ty * 4 + i)) s = -1e30f;
                Ss[(ty * 4 + i) * PAD + tx * 4 + j] = s;
            }
        }
        __syncthreads();

        // Online softmax: 4 threads per row
        {
            const int row = tid >> 2, part = tid & 3;
            float* srow = Ss + row * PAD + part * 16;
            float mx = -1e30f;
#pragma unroll
            for (int c = 0; c < 16; c++) mx = fmaxf(mx, srow[c]);
            mx = fmaxf(mx, __shfl_xor_sync(0xffffffffu, mx, 1));
            mx = fmaxf(mx, __shfl_xor_sync(0xffffffffu, mx, 2));
            const float mold = mrow[row];
            const float mnew = fmaxf(mold, mx);
            const float corr = __expf(mold - mnew);
            float sum = 0.0f;
#pragma unroll
            for (int c = 0; c < 16; c++) {
                float pv = __expf(srow[c] - mnew);
                srow[c] = pv;
                sum += pv;
            }
            sum += __shfl_xor_sync(0xffffffffu, sum, 1);
            sum += __shfl_xor_sync(0xffffffffu, sum, 2);
            if (part == 0) {
                mrow[row] = mnew;
                lrow[row] = lrow[row] * corr + sum;
                crow[row] = corr;
            }
        }
        __syncthreads();

        // Rescale accumulators, then O += P @ V
        float cr0 = crow[ty * 4 + 0], cr1 = crow[ty * 4 + 1];
        float cr2 = crow[ty * 4 + 2], cr3 = crow[ty * 4 + 3];
#pragma unroll
        for (int j = 0; j < 4; j++) {
            o[0][j] *= cr0; o[1][j] *= cr1; o[2][j] *= cr2; o[3][j] *= cr3;
        }
#pragma unroll 4
        for (int k = 0; k < 64; k++) {
            float p0 = Ss[(ty * 4 + 0) * PAD + k];
            float p1 = Ss[(ty * 4 + 1) * PAD + k];
            float p2 = Ss[(ty * 4 + 2) * PAD + k];
            float p3 = Ss[(ty * 4 + 3) * PAD + k];
            float4 v4 = *(const float4*)&Vs[k * PAD + tx * 4];
            o[0][0] += p0 * v4.x; o[0][1] += p0 * v4.y;
            o[0][2] += p0 * v4.z; o[0][3] += p0 * v4.w;
            o[1][0] += p1 * v4.x; o[1][1] += p1 * v4.y;
            o[1][2] += p1 * v4.z; o[1][3] += p1 * v4.w;
            o[2][0] += p2 * v4.x; o[2][1] += p2 * v4.y;
            o[2][2] += p2 * v4.z; o[2][3] += p2 * v4.w;
            o[3][0] += p3 * v4.x; o[3][1] += p3 * v4.y;
            o[3][2] += p3 * v4.z; o[3][3] += p3 * v4.w;
        }
        __syncthreads();
    }

    // Epilogue: divide by l, write to g_A [(b*T + q)][h*64 + d]
#pragma unroll
    for (int i = 0; i < 4; i++) {
        float inv_l = 1.0f / lrow[ty * 4 + i];
        float4 ov;
        ov.x = o[i][0] * inv_l;
        ov.y = o[i][1] * inv_l;
        ov.z = o[i][2] * inv_l;
        ov.w = o[i][3] * inv_l;
        *(float4*)&g_A[(size_t)(b * TT + q0 + ty * 4 + i) * CC + h * HD + tx * 4] = ov;
    }
}

// ---------------------------------------------------------------------------
extern "C" void kernel_launch(void* const* d_in, const int* in_sizes, int n_in,
                              void* d_out, int out_size) {
    const float* x   = (const float*)d_in[0];
    const int*   pos = (const int*)d_in[1];
    const float* q_w = (const float*)d_in[2];
    const float* q_b = (const float*)d_in[3];
    const float* k_w = (const float*)d_in[4];
    const float* k_b = (const float*)d_in[5];
    const float* v_w = (const float*)d_in[6];
    const float* v_b = (const float*)d_in[7];
    const float* o_w = (const float*)d_in[8];
    const float* o_b = (const float*)d_in[9];
    float* out = (float*)d_out;

    float *Qp, *Kp, *Vp, *Ap;
    cudaGetSymbolAddress((void**)&Qp, g_Q);
    cudaGetSymbolAddress((void**)&Kp, g_K);
    cudaGetSymbolAddress((void**)&Vp, g_V);
    cudaGetSymbolAddress((void**)&Ap, g_A);

    const int M = BB * TT;  // 8192

    // QKV projections
    sgemm64<<<dim3(CC / 64, M / 64), 256>>>(x, q_w, q_b, Qp, M, CC, CC);
    sgemm64<<<dim3((NKV * HD) / 64, M / 64), 256>>>(x, k_w, k_b, Kp, M, NKV * HD, CC);
    sgemm64<<<dim3((NKV * HD) / 64, M / 64), 256>>>(x, v_w, v_b, Vp, M, NKV * HD, CC);

    // RoPE on Q and K
    {
        int totQ = BB * TT * NH;
        int totK = BB * TT * NKV;
        rope_kernel<<<(totQ + 7) / 8, 256>>>(Qp, pos, NH, totQ);
        rope_kernel<<<(totK + 7) / 8, 256>>>(Kp, pos, NKV, totK);
    }

    // Attention
    {
        const int smem_bytes = (4 * 64 * PAD + 3 * 64) * (int)sizeof(float);  // 70400
        cudaFuncSetAttribute(attn_kernel, cudaFuncAttributeMaxDynamicSharedMemorySize,
                             smem_bytes);
        attn_kernel<<<dim3(TT / 64, NH, BB), 256, smem_bytes>>>();
    }

    // Output projection -> d_out
    sgemm64<<<dim3(CC / 64, M / 64), 256>>>(Ap, o_w, o_b, out, M, CC, CC);
}

// round 2
// speedup vs baseline: 1.5228x; 1.5228x over previous
#include <cuda_runtime.h>
#include <math.h>
#include <stdint.h>

// Shapes
#define BB 8
#define TT 1024
#define CC 768
#define NH 12
#define NKV 4
#define HD 64
#define REP 3

// Scratch (no allocations allowed)
__device__ float g_Q[BB * TT * CC];        // [b*T+t][h*64+d]
__device__ float g_K[BB * TT * NKV * HD];  // [b*T+t][kvh*64+d]
__device__ float g_V[BB * TT * NKV * HD];
__device__ float g_A[BB * TT * CC];        // attention output

// ---------------------------------------------------------------------------
// tf32 helpers
// ---------------------------------------------------------------------------
__device__ __forceinline__ uint32_t to_tf32(float a) {
    uint32_t r;
    asm("cvt.rna.tf32.f32 %0, %1;" : "=r"(r) : "f"(a));
    return r;
}
__device__ __forceinline__ void split_tf32(float a, uint32_t& hi, uint32_t& lo) {
    asm("cvt.rna.tf32.f32 %0, %1;" : "=r"(hi) : "f"(a));
    float r = a - __uint_as_float(hi);
    asm("cvt.rna.tf32.f32 %0, %1;" : "=r"(lo) : "f"(r));
}
__device__ __forceinline__ void mma_tf32(float c[4], uint32_t a0, uint32_t a1,
                                         uint32_t a2, uint32_t a3,
                                         uint32_t b0, uint32_t b1) {
    asm volatile(
        "mma.sync.aligned.m16n8k8.row.col.f32.tf32.tf32.f32 "
        "{%0,%1,%2,%3}, {%4,%5,%6,%7}, {%8,%9}, {%0,%1,%2,%3};"
        : "+f"(c[0]), "+f"(c[1]), "+f"(c[2]), "+f"(c[3])
        : "r"(a0), "r"(a1), "r"(a2), "r"(a3), "r"(b0), "r"(b1));
}

// ---------------------------------------------------------------------------
// tf32x3 GEMM: C[M,N] = A[M,K] @ W[K,N] + bias[N]   (fp32-accurate)
// Block tile 128x64, BK=16, 256 threads (8 warps), warp tile 32x32.
// ---------------------------------------------------------------------------
#define BM 128
#define BN 64
#define BK 16

__global__ __launch_bounds__(256, 2)
void gemm_tf32x3(const float* __restrict__ A, const float* __restrict__ W,
                 const float* __restrict__ bias, float* __restrict__ C,
                 int M, int N, int K) {
    __shared__ float As[BM][BK + 4];   // [m][k], stride 20 -> conflict-free frag LDS
    __shared__ float Bs[BK][BN + 4];   // [k][n], stride 68

    const int tid = threadIdx.x;
    const int wid = tid >> 5;
    const int lane = tid & 31;
    const int group = lane >> 2;       // 0..7
    const int tig = lane & 3;          // 0..3
    const int warpm = wid >> 1;        // 0..3
    const int warpn = wid & 1;         // 0..1
    const int m0 = blockIdx.y * BM;
    const int n0 = blockIdx.x * BN;

    float acc[2][4][4];                // [mt][nt][c]
#pragma unroll
    for (int i = 0; i < 2; i++)
#pragma unroll
        for (int j = 0; j < 4; j++)
#pragma unroll
            for (int c = 0; c < 4; c++) acc[i][j][c] = 0.0f;

    for (int kt = 0; kt < K; kt += BK) {
        // Load A tile (128x16): 2 float4 per thread
#pragma unroll
        for (int r = 0; r < 2; r++) {
            int idx = tid + r * 256;
            int m = idx >> 2, kq = idx & 3;
            float4 v = *(const float4*)&A[(size_t)(m0 + m) * K + kt + kq * 4];
            *(float4*)&As[m][kq * 4] = v;
        }
        // Load B tile (16x64): 1 float4 per thread
        {
            int k = tid >> 4, nq = tid & 15;
            float4 v = *(const float4*)&W[(size_t)(kt + k) * N + n0 + nq * 4];
            *(float4*)&Bs[k][nq * 4] = v;
        }
        __syncthreads();

#pragma unroll
        for (int ks = 0; ks < 2; ks++) {
            const int kk = ks * 8;
            // A fragments (hi/lo), 2 m-tiles
            uint32_t ah[2][4], al[2][4];
#pragma unroll
            for (int mt = 0; mt < 2; mt++) {
                int mrow = warpm * 32 + mt * 16 + group;
                split_tf32(As[mrow][kk + tig], ah[mt][0], al[mt][0]);
                split_tf32(As[mrow + 8][kk + tig], ah[mt][1], al[mt][1]);
                split_tf32(As[mrow][kk + tig + 4], ah[mt][2], al[mt][2]);
                split_tf32(As[mrow + 8][kk + tig + 4], ah[mt][3], al[mt][3]);
            }
            // B fragments (hi/lo), 4 n-tiles
            uint32_t bh[4][2], bl[4][2];
#pragma unroll
            for (int nt = 0; nt < 4; nt++) {
                int ncol = warpn * 32 + nt * 8 + group;
                split_tf32(Bs[kk + tig][ncol], bh[nt][0], bl[nt][0]);
                split_tf32(Bs[kk + tig + 4][ncol], bh[nt][1], bl[nt][1]);
            }
#pragma unroll
            for (int mt = 0; mt < 2; mt++) {
#pragma unroll
                for (int nt = 0; nt < 4; nt++) {
                    mma_tf32(acc[mt][nt], ah[mt][0], ah[mt][1], ah[mt][2], ah[mt][3],
                             bh[nt][0], bh[nt][1]);
                    mma_tf32(acc[mt][nt], al[mt][0], al[mt][1], al[mt][2], al[mt][3],
                             bh[nt][0], bh[nt][1]);
                    mma_tf32(acc[mt][nt], ah[mt][0], ah[mt][1], ah[mt][2], ah[mt][3],
                             bl[nt][0], bl[nt][1]);
                }
            }
        }
        __syncthreads();
    }

    // Epilogue with bias
#pragma unroll
    for (int mt = 0; mt < 2; mt++) {
        int r0 = m0 + warpm * 32 + mt * 16 + group;
#pragma unroll
        for (int nt = 0; nt < 4; nt++) {
            int col = n0 + warpn * 32 + nt * 8 + 2 * tig;
            float b0v = bias[col], b1v = bias[col + 1];
            float2 v0 = make_float2(acc[mt][nt][0] + b0v, acc[mt][nt][1] + b1v);
            float2 v1 = make_float2(acc[mt][nt][2] + b0v, acc[mt][nt][3] + b1v);
            *(float2*)&C[(size_t)r0 * N + col] = v0;
            *(float2*)&C[(size_t)(r0 + 8) * N + col] = v1;
        }
    }
}

// ---------------------------------------------------------------------------
// RoPE (torch-style interleaved rotate_half), in place. One warp per vector.
// ---------------------------------------------------------------------------
__global__ void rope_kernel(float* __restrict__ buf, const int* __restrict__ pos,
                            int nHeads, int total) {
    __shared__ float sv[8][64];
    const int warp = threadIdx.x >> 5;
    const int lane = threadIdx.x & 31;
    const int vec = blockIdx.x * 8 + warp;
    if (vec >= total) return;

    const int h = vec % nHeads;
    const int bt = vec / nHeads;
    const int t = bt % TT;
    float* p = buf + (size_t)bt * (nHeads * HD) + h * HD;

    sv[warp][lane] = p[lane];
    sv[warp][lane + 32] = p[lane + 32];
    __syncwarp();

    const float po = (float)pos[t];
    const float freq = exp2f(-(float)lane * (13.287712379549449f / 32.0f));
    float sn, cs;
    sincosf(po * freq, &sn, &cs);

    const int j = lane;
    const float xj = sv[warp][j];
    const float xj32 = sv[warp][j + 32];
    const float rot_lo = (j & 1) ? -sv[warp][47 + ((j + 1) >> 1)]
                                 : -sv[warp][16 + (j >> 1)];
    const float rot_hi = (j & 1) ? sv[warp][32 + ((j - 1) >> 1)]
                                 : sv[warp][j >> 1];
    p[j] = xj * cs + rot_lo * sn;
    p[j + 32] = xj32 * cs + rot_hi * sn;
}

// ---------------------------------------------------------------------------
// Flash attention with tf32 MMA (x1). 4 warps, each owns 16 query rows.
// Block = (64-query tile, head, batch). Online softmax in registers.
// Dynamic smem: Qs, Ks, Vs, Ps each [64][68] fp32.
// ---------------------------------------------------------------------------
#define APAD 68
__global__ __launch_bounds__(128)
void attn_mma_kernel() {
    extern __shared__ float sm[];
    float* Qs = sm;                    // [64][68]  [row][d]
    float* Ks = Qs + 64 * APAD;        // [64][68]  [key][d]
    float* Vs = Ks + 64 * APAD;        // [64][68]  [key][d]
    float* Ps = Vs + 64 * APAD;        // [64][68]  [row][key] (per-warp slices)

    const int tid = threadIdx.x;
    const int wid = tid >> 5;
    const int lane = tid & 31;
    const int group = lane >> 2;
    const int tig = lane & 3;
    const int q0 = blockIdx.x * 64;
    const int h = blockIdx.y;
    const int b = blockIdx.z;
    const int kvh = h / REP;
    const int qbase = wid * 16;        // warp's first local query row

    const float* Qg = g_Q + (size_t)b * TT * CC + h * HD;
    const float* Kg = g_K + (size_t)b * TT * (NKV * HD) + kvh * HD;
    const float* Vg = g_V + (size_t)b * TT * (NKV * HD) + kvh * HD;

    // Load Q tile
#pragma unroll
    for (int r = 0; r < 8; r++) {
        int idx = tid + r * 128;
        int row = idx >> 4, dq = idx & 15;
        float4 v = *(const float4*)&Qg[(size_t)(q0 + row) * CC + dq * 4];
        *(float4*)&Qs[row * APAD + dq * 4] = v;
    }

    float mr0 = -1e30f, mr1 = -1e30f, lr0 = 0.0f, lr1 = 0.0f;
    float o[8][4];
#pragma unroll
    for (int nt = 0; nt < 8; nt++)
#pragma unroll
        for (int c = 0; c < 4; c++) o[nt][c] = 0.0f;

    const int row0g = q0 + qbase + group;      // global query row (c0,c1)
    const int row1g = row0g + 8;               // global query row (c2,c3)

    for (int j0 = 0; j0 <= q0; j0 += 64) {
        __syncthreads();  // prior iteration's reads done before overwrite
        // Load K,V tiles
#pragma unroll
        for (int r = 0; r < 8; r++) {
            int idx = tid + r * 128;
            int row = idx >> 4, dq = idx & 15;
            size_t goff = (size_t)(j0 + row) * (NKV * HD) + dq * 4;
            *(float4*)&Ks[row * APAD + dq * 4] = *(const float4*)&Kg[goff];
            *(float4*)&Vs[row * APAD + dq * 4] = *(const float4*)&Vg[goff];
        }
        __syncthreads();

        // ---- S = Q K^T ----
        float s[8][4];
#pragma unroll
        for (int nt = 0; nt < 8; nt++)
#pragma unroll
            for (int c = 0; c < 4; c++) s[nt][c] = 0.0f;

#pragma unroll
        for (int ks = 0; ks < 8; ks++) {
            const int kk = ks * 8;
            const int qr = qbase + group;
            uint32_t a0 = to_tf32(Qs[qr * APAD + kk + tig]);
            uint32_t a1 = to_tf32(Qs[(qr + 8) * APAD + kk + tig]);
            uint32_t a2 = to_tf32(Qs[qr * APAD + kk + tig + 4]);
            uint32_t a3 = to_tf32(Qs[(qr + 8) * APAD + kk + tig + 4]);
#pragma unroll
            for (int nt = 0; nt < 8; nt++) {
                int key = nt * 8 + group;
                uint32_t b0 = to_tf32(Ks[key * APAD + kk + tig]);
                uint32_t b1 = to_tf32(Ks[key * APAD + kk + tig + 4]);
                mma_tf32(s[nt], a0, a1, a2, a3, b0, b1);
            }
        }

        // ---- scale + causal mask ----
        const bool diag = (j0 == q0);
#pragma unroll
        for (int nt = 0; nt < 8; nt++) {
            int colg = j0 + nt * 8 + 2 * tig;
            s[nt][0] *= 0.125f; s[nt][1] *= 0.125f;
            s[nt][2] *= 0.125f; s[nt][3] *= 0.125f;
            if (diag) {
                if (colg > row0g) s[nt][0] = -1e30f;
                if (colg + 1 > row0g) s[nt][1] = -1e30f;
                if (colg > row1g) s[nt][2] = -1e30f;
                if (colg + 1 > row1g) s[nt][3] = -1e30f;
            }
        }

        // ---- online softmax (rows row0g, row1g) ----
        float mx0 = -1e30f, mx1 = -1e30f;
#pragma unroll
        for (int nt = 0; nt < 8; nt++) {
            mx0 = fmaxf(mx0, fmaxf(s[nt][0], s[nt][1]));
            mx1 = fmaxf(mx1, fmaxf(s[nt][2], s[nt][3]));
        }
        mx0 = fmaxf(mx0, __shfl_xor_sync(0xffffffffu, mx0, 1));
        mx0 = fmaxf(mx0, __shfl_xor_sync(0xffffffffu, mx0, 2));
        mx1 = fmaxf(mx1, __shfl_xor_sync(0xffffffffu, mx1, 1));
        mx1 = fmaxf(mx1, __shfl_xor_sync(0xffffffffu, mx1, 2));

        float mn0 = fmaxf(mr0, mx0), mn1 = fmaxf(mr1, mx1);
        float corr0 = __expf(mr0 - mn0), corr1 = __expf(mr1 - mn1);
        float sum0 = 0.0f, sum1 = 0.0f;
#pragma unroll
        for (int nt = 0; nt < 8; nt++) {
            s[nt][0] = __expf(s[nt][0] - mn0);
            s[nt][1] = __expf(s[nt][1] - mn0);
            s[nt][2] = __expf(s[nt][2] - mn1);
            s[nt][3] = __expf(s[nt][3] - mn1);
            sum0 += s[nt][0] + s[nt][1];
            sum1 += s[nt][2] + s[nt][3];
        }
        sum0 += __shfl_xor_sync(0xffffffffu, sum0, 1);
        sum0 += __shfl_xor_sync(0xffffffffu, sum0, 2);
        sum1 += __shfl_xor_sync(0xffffffffu, sum1, 1);
        sum1 += __shfl_xor_sync(0xffffffffu, sum1, 2);
        lr0 = lr0 * corr0 + sum0;
        lr1 = lr1 * corr1 + sum1;
        mr0 = mn0; mr1 = mn1;

        // rescale O
#pragma unroll
        for (int nt = 0; nt < 8; nt++) {
            o[nt][0] *= corr0; o[nt][1] *= corr0;
            o[nt][2] *= corr1; o[nt][3] *= corr1;
        }

        // ---- store P to per-warp smem slice ----
        {
            int r0 = qbase + group;
#pragma unroll
            for (int nt = 0; nt < 8; nt++) {
                int col = nt * 8 + 2 * tig;
                *(float2*)&Ps[r0 * APAD + col] = make_float2(s[nt][0], s[nt][1]);
                *(float2*)&Ps[(r0 + 8) * APAD + col] = make_float2(s[nt][2], s[nt][3]);
            }
        }
        __syncwarp();

        // ---- O += P V ----
#pragma unroll
        for (int ks = 0; ks < 8; ks++) {
            const int kk = ks * 8;
            const int r0 = qbase + group;
            uint32_t a0 = to_tf32(Ps[r0 * APAD + kk + tig]);
            uint32_t a1 = to_tf32(Ps[(r0 + 8) * APAD + kk + tig]);
            uint32_t a2 = to_tf32(Ps[r0 * APAD + kk + tig + 4]);
            uint32_t a3 = to_tf32(Ps[(r0 + 8) * APAD + kk + tig + 4]);
#pragma unroll
            for (int nt = 0; nt < 8; nt++) {
                int d = nt * 8 + group;
                uint32_t b0 = to_tf32(Vs[(kk + tig) * APAD + d]);
                uint32_t b1 = to_tf32(Vs[(kk + tig + 4) * APAD + d]);
                mma_tf32(o[nt], a0, a1, a2, a3, b0, b1);
            }
        }
    }

    // Epilogue: normalize and write
    float inv0 = 1.0f / lr0, inv1 = 1.0f / lr1;
    float* Ag = g_A + (size_t)b * TT * CC + h * HD;
#pragma unroll
    for (int nt = 0; nt < 8; nt++) {
        int col = nt * 8 + 2 * tig;
        *(float2*)&Ag[(size_t)(q0 + qbase + group) * CC + col] =
            make_float2(o[nt][0] * inv0, o[nt][1] * inv0);
        *(float2*)&Ag[(size_t)(q0 + qbase + group + 8) * CC + col] =
            make_float2(o[nt][2] * inv1, o[nt][3] * inv1);
    }
}

// ---------------------------------------------------------------------------
extern "C" void kernel_launch(void* const* d_in, const int* in_sizes, int n_in,
                              void* d_out, int out_size) {
    const float* x   = (const float*)d_in[0];
    const int*   pos = (const int*)d_in[1];
    const float* q_w = (const float*)d_in[2];
    const float* q_b = (const float*)d_in[3];
    const float* k_w = (const float*)d_in[4];
    const float* k_b = (const float*)d_in[5];
    const float* v_w = (const float*)d_in[6];
    const float* v_b = (const float*)d_in[7];
    const float* o_w = (const float*)d_in[8];
    const float* o_b = (const float*)d_in[9];
    float* out = (float*)d_out;

    float *Qp, *Kp, *Vp, *Ap;
    cudaGetSymbolAddress((void**)&Qp, g_Q);
    cudaGetSymbolAddress((void**)&Kp, g_K);
    cudaGetSymbolAddress((void**)&Vp, g_V);
    cudaGetSymbolAddress((void**)&Ap, g_A);

    const int M = BB * TT;  // 8192

    // QKV projections (tf32x3 tensor-core GEMM)
    gemm_tf32x3<<<dim3(CC / BN, M / BM), 256>>>(x, q_w, q_b, Qp, M, CC, CC);
    gemm_tf32x3<<<dim3((NKV * HD) / BN, M / BM), 256>>>(x, k_w, k_b, Kp, M, NKV * HD, CC);
    gemm_tf32x3<<<dim3((NKV * HD) / BN, M / BM), 256>>>(x, v_w, v_b, Vp, M, NKV * HD, CC);

    // RoPE on Q and K
    {
        int totQ = BB * TT * NH;
        int totK = BB * TT * NKV;
        rope_kernel<<<(totQ + 7) / 8, 256>>>(Qp, pos, NH, totQ);
        rope_kernel<<<(totK + 7) / 8, 256>>>(Kp, pos, NKV, totK);
    }

    // Attention (tf32 MMA flash)
    {
        const int smem_bytes = 4 * 64 * APAD * (int)sizeof(float);  // 69632
        cudaFuncSetAttribute(attn_mma_kernel,
                             cudaFuncAttributeMaxDynamicSharedMemorySize, smem_bytes);
        attn_mma_kernel<<<dim3(TT / 64, NH, BB), 128, smem_bytes>>>();
    }

    // Output projection -> d_out
    gemm_tf32x3<<<dim3(CC / BN, M / BM), 256>>>(Ap, o_w, o_b, out, M, CC, CC);
}

// round 4
// speedup vs baseline: 2.2919x; 1.5050x over previous
#include <cuda_runtime.h>
#include <cuda_bf16.h>
#include <math.h>
#include <stdint.h>

// Shapes
#define BB 8
#define TT 1024
#define CC 768
#define NH 12
#define NKV 4
#define HD 64
#define REP 3
#define MM (BB * TT)   // 8192

// Scratch (no allocations allowed)
__device__ float g_Q[MM * CC];
__device__ float g_K[MM * NKV * HD];
__device__ float g_V[MM * NKV * HD];
__device__ float g_A[MM * CC];

// bf16 split scratch
__device__ __nv_bfloat16 g_xhi[MM * CC], g_xlo[MM * CC];
__device__ __nv_bfloat16 g_ahi[MM * CC], g_alo[MM * CC];
__device__ __nv_bfloat16 g_wq_hi[CC * CC], g_wq_lo[CC * CC];     // [N=768][K=768]
__device__ __nv_bfloat16 g_wk_hi[NKV * HD * CC], g_wk_lo[NKV * HD * CC];
__device__ __nv_bfloat16 g_wv_hi[NKV * HD * CC], g_wv_lo[NKV * HD * CC];
__device__ __nv_bfloat16 g_wo_hi[CC * CC], g_wo_lo[CC * CC];

// ---------------------------------------------------------------------------
// helpers
// ---------------------------------------------------------------------------
__device__ __forceinline__ uint32_t to_tf32(float a) {
    uint32_t r;
    asm("cvt.rna.tf32.f32 %0, %1;" : "=r"(r) : "f"(a));
    return r;
}
__device__ __forceinline__ void mma_tf32(float c[4], uint32_t a0, uint32_t a1,
                                         uint32_t a2, uint32_t a3,
                                         uint32_t b0, uint32_t b1) {
    asm volatile(
        "mma.sync.aligned.m16n8k8.row.col.f32.tf32.tf32.f32 "
        "{%0,%1,%2,%3}, {%4,%5,%6,%7}, {%8,%9}, {%0,%1,%2,%3};"
        : "+f"(c[0]), "+f"(c[1]), "+f"(c[2]), "+f"(c[3])
        : "r"(a0), "r"(a1), "r"(a2), "r"(a3), "r"(b0), "r"(b1));
}
__device__ __forceinline__ void mma_bf16(float c[4], const uint32_t a[4],
                                         const uint32_t b[2]) {
    asm volatile(
        "mma.sync.aligned.m16n8k16.row.col.f32.bf16.bf16.f32 "
        "{%0,%1,%2,%3}, {%4,%5,%6,%7}, {%8,%9}, {%0,%1,%2,%3};"
        : "+f"(c[0]), "+f"(c[1]), "+f"(c[2]), "+f"(c[3])
        : "r"(a[0]), "r"(a[1]), "r"(a[2]), "r"(a[3]), "r"(b[0]), "r"(b[1]));
}
__device__ __forceinline__ void cp16(void* dst_smem, const void* src) {
    uint32_t d = (uint32_t)__cvta_generic_to_shared(dst_smem);
    asm volatile("cp.async.cg.shared.global [%0], [%1], 16;" :: "r"(d), "l"(src));
}
__device__ __forceinline__ void split_one(float v, __nv_bfloat16& h, __nv_bfloat16& l) {
    h = __float2bfloat16_rn(v);
    l = __float2bfloat16_rn(v - __bfloat162float(h));
}

// ---------------------------------------------------------------------------
// Elementwise split: fp32 -> hi/lo bf16. 2 elements per thread.
// ---------------------------------------------------------------------------
__global__ void split_ew(const float* __restrict__ in, __nv_bfloat16* __restrict__ hi,
                         __nv_bfloat16* __restrict__ lo, int n) {
    int i = (blockIdx.x * blockDim.x + threadIdx.x) * 2;
    if (i >= n) return;
    float2 v = *(const float2*)&in[i];
    __nv_bfloat16 h0, l0, h1, l1;
    split_one(v.x, h0, l0);
    split_one(v.y, h1, l1);
    *(__nv_bfloat162*)&hi[i] = __nv_bfloat162(h0, h1);
    *(__nv_bfloat162*)&lo[i] = __nv_bfloat162(l0, l1);
}

// ---------------------------------------------------------------------------
// Transpose + split: W[K][N] fp32 -> hi/lo[N][K] bf16. 32x32 tiles.
// ---------------------------------------------------------------------------
__global__ void split_T(const float* __restrict__ W, __nv_bfloat16* __restrict__ hi,
                        __nv_bfloat16* __restrict__ lo, int K, int N) {
    __shared__ float t[32][33];
    const int n0 = blockIdx.x * 32, k0 = blockIdx.y * 32;
    const int tx = threadIdx.x, ty = threadIdx.y;
#pragma unroll
    for (int j = 0; j < 4; j++)
        t[ty + j * 8][tx] = W[(size_t)(k0 + ty + j * 8) * N + n0 + tx];
    __syncthreads();
#pragma unroll
    for (int j = 0; j < 4; j++) {
        int r = ty + j * 8;
        float v = t[tx][r];
        __nv_bfloat16 h, l;
        split_one(v, h, l);
        hi[(size_t)(n0 + r) * K + k0 + tx] = h;
        lo[(size_t)(n0 + r) * K + k0 + tx] = l;
    }
}

// ---------------------------------------------------------------------------
// bf16x3 GEMM: C[M,N] = Ah/Al[M,K] @ (Bh/Bl[N,K])^T + bias
// Block 128x128, BK=32, 256 threads, warp tile 64x32, cp.async double buffer.
// smem rows padded to 80B (20 words) -> conflict-free fragment LDS.
// ---------------------------------------------------------------------------
#define GBM 128
#define GBN 128
#define GBK 32
#define GROW 40          // bf16 per smem row (80B)
#define GROWW 20         // uint32 words per row
#define STAGE_B 40960    // bytes per stage (4 arrays * 128 * 80)
#define ARR_B 10240      // bytes per array

__global__ __launch_bounds__(256)
void gemm_bf16x3(const __nv_bfloat16* __restrict__ Ah, const __nv_bfloat16* __restrict__ Al,
                 const __nv_bfloat16* __restrict__ Bh, const __nv_bfloat16* __restrict__ Bl,
                 const float* __restrict__ bias, float* __restrict__ C,
                 int M, int N, int K) {
    extern __shared__ char smem_raw[];

    const int tid = threadIdx.x;
    const int wid = tid >> 5;
    const int lane = tid & 31;
    const int group = lane >> 2;
    const int tig = lane & 3;
    const int warpm = wid & 1;      // 2 along M (64 each)
    const int warpn = wid >> 1;     // 4 along N (32 each)
    const int m0 = blockIdx.y * GBM;
    const int n0 = blockIdx.x * GBN;

    const __nv_bfloat16* gsrc[4] = {Ah, Al, Bh, Bl};

    auto load_stage = [&](int stage, int kt) {
        char* sbase = smem_raw + stage * STAGE_B;
#pragma unroll
        for (int i = 0; i < 8; i++) {
            int cid = tid + i * 256;          // 0..2047
            int arr = cid >> 9;               // 0..3
            int within = cid & 511;
            int row = within >> 2;            // 0..127
            int c = within & 3;               // 16B chunk
            int grow = (arr < 2) ? (m0 + row) : (n0 + row);
            const __nv_bfloat16* src = gsrc[arr] + (size_t)grow * K + kt + c * 8;
            cp16(sbase + arr * ARR_B + row * 80 + c * 16, src);
        }
        asm volatile("cp.async.commit_group;");
    };

    float acc[4][4][4];
#pragma unroll
    for (int mt = 0; mt < 4; mt++)
#pragma unroll
        for (int nt = 0; nt < 4; nt++)
#pragma unroll
            for (int c = 0; c < 4; c++) acc[mt][nt][c] = 0.0f;

    const int ntiles = K / GBK;
    load_stage(0, 0);

    for (int t = 0; t < ntiles; t++) {
        if (t + 1 < ntiles) {
            load_stage((t + 1) & 1, (t + 1) * GBK);
            asm volatile("cp.async.wait_group 1;");
        } else {
            asm volatile("cp.async.wait_group 0;");
        }
        __syncthreads();

        const char* sbase = smem_raw + (t & 1) * STAGE_B;
        const uint32_t* sAh = (const uint32_t*)(sbase);
        const uint32_t* sAl = (const uint32_t*)(sbase + ARR_B);
        const uint32_t* sBh = (const uint32_t*)(sbase + 2 * ARR_B);
        const uint32_t* sBl = (const uint32_t*)(sbase + 3 * ARR_B);

#pragma unroll
        for (int s = 0; s < 2; s++) {
            const int w0 = s * 8;
            uint32_t ahi[4][4], alo[4][4], bhi[4][2], blo[4][2];
#pragma unroll
            for (int mt = 0; mt < 4; mt++) {
                int r = warpm * 64 + mt * 16 + group;
                ahi[mt][0] = sAh[r * GROWW + w0 + tig];
                ahi[mt][1] = sAh[(r + 8) * GROWW + w0 + tig];
                ahi[mt][2] = sAh[r * GROWW + w0 + tig + 4];
                ahi[mt][3] = sAh[(r + 8) * GROWW + w0 + tig + 4];
                alo[mt][0] = sAl[r * GROWW + w0 + tig];
                alo[mt][1] = sAl[(r + 8) * GROWW + w0 + tig];
                alo[mt][2] = sAl[r * GROWW + w0 + tig + 4];
                alo[mt][3] = sAl[(r + 8) * GROWW + w0 + tig + 4];
            }
#pragma unroll
            for (int nt = 0; nt < 4; nt++) {
                int n = warpn * 32 + nt * 8 + group;
                bhi[nt][0] = sBh[n * GROWW + w0 + tig];
                bhi[nt][1] = sBh[n * GROWW + w0 + tig + 4];
                blo[nt][0] = sBl[n * GROWW + w0 + tig];
                blo[nt][1] = sBl[n * GROWW + w0 + tig + 4];
            }
#pragma unroll
            for (int mt = 0; mt < 4; mt++)
#pragma unroll
                for (int nt = 0; nt < 4; nt++) {
                    mma_bf16(acc[mt][nt], ahi[mt], bhi[nt]);
                    mma_bf16(acc[mt][nt], alo[mt], bhi[nt]);
                    mma_bf16(acc[mt][nt], ahi[mt], blo[nt]);
                }
        }
        __syncthreads();
    }

    // Epilogue
#pragma unroll
    for (int mt = 0; mt < 4; mt++) {
        int r = m0 + warpm * 64 + mt * 16 + group;
#pragma unroll
        for (int nt = 0; nt < 4; nt++) {
            int col = n0 + warpn * 32 + nt * 8 + 2 * tig;
            float b0v = bias[col], b1v = bias[col + 1];
            *(float2*)&C[(size_t)r * N + col] =
                make_float2(acc[mt][nt][0] + b0v, acc[mt][nt][1] + b1v);
            *(float2*)&C[(size_t)(r + 8) * N + col] =
                make_float2(acc[mt][nt][2] + b0v, acc[mt][nt][3] + b1v);
        }
    }
}

// ---------------------------------------------------------------------------
// RoPE (torch-style interleaved rotate_half), in place. One warp per vector.
// ---------------------------------------------------------------------------
__global__ void rope_kernel(float* __restrict__ buf, const int* __restrict__ pos,
                            int nHeads, int total) {
    __shared__ float sv[8][64];
    const int warp = threadIdx.x >> 5;
    const int lane = threadIdx.x & 31;
    const int vec = blockIdx.x * 8 + warp;
    if (vec >= total) return;

    const int h = vec % nHeads;
    const int bt = vec / nHeads;
    const int t = bt % TT;
    float* p = buf + (size_t)bt * (nHeads * HD) + h * HD;

    sv[warp][lane] = p[lane];
    sv[warp][lane + 32] = p[lane + 32];
    __syncwarp();

    const float po = (float)pos[t];
    const float freq = exp2f(-(float)lane * (13.287712379549449f / 32.0f));
    float sn, cs;
    sincosf(po * freq, &sn, &cs);

    const int j = lane;
    const float xj = sv[warp][j];
    const float xj32 = sv[warp][j + 32];
    const float rot_lo = (j & 1) ? -sv[warp][47 + ((j + 1) >> 1)]
                                 : -sv[warp][16 + (j >> 1)];
    const float rot_hi = (j & 1) ? sv[warp][32 + ((j - 1) >> 1)]
                                 : sv[warp][j >> 1];
    p[j] = xj * cs + rot_lo * sn;
    p[j + 32] = xj32 * cs + rot_hi * sn;
}

// ---------------------------------------------------------------------------
// Flash attention with tf32 MMA (x1). 4 warps, each owns 16 query rows.
// ---------------------------------------------------------------------------
#define APAD 68
__global__ __launch_bounds__(128)
void attn_mma_kernel() {
    extern __shared__ float sm[];
    float* Qs = sm;
    float* Ks = Qs + 64 * APAD;
    float* Vs = Ks + 64 * APAD;
    float* Ps = Vs + 64 * APAD;

    const int tid = threadIdx.x;
    const int wid = tid >> 5;
    const int lane = tid & 31;
    const int group = lane >> 2;
    const int tig = lane & 3;
    const int q0 = blockIdx.x * 64;
    const int h = blockIdx.y;
    const int b = blockIdx.z;
    const int kvh = h / REP;
    const int qbase = wid * 16;

    const float* Qg = g_Q + (size_t)b * TT * CC + h * HD;
    const float* Kg = g_K + (size_t)b * TT * (NKV * HD) + kvh * HD;
    const float* Vg = g_V + (size_t)b * TT * (NKV * HD) + kvh * HD;

#pragma unroll
    for (int r = 0; r < 8; r++) {
        int idx = tid + r * 128;
        int row = idx >> 4, dq = idx & 15;
        float4 v = *(const float4*)&Qg[(size_t)(q0 + row) * CC + dq * 4];
        *(float4*)&Qs[row * APAD + dq * 4] = v;
    }

    float mr0 = -1e30f, mr1 = -1e30f, lr0 = 0.0f, lr1 = 0.0f;
    float o[8][4];
#pragma unroll
    for (int nt = 0; nt < 8; nt++)
#pragma unroll
        for (int c = 0; c < 4; c++) o[nt][c] = 0.0f;

    const int row0g = q0 + qbase + group;
    const int row1g = row0g + 8;

    for (int j0 = 0; j0 <= q0; j0 += 64) {
        __syncthreads();
#pragma unroll
        for (int r = 0; r < 8; r++) {
            int idx = tid + r * 128;
            int row = idx >> 4, dq = idx & 15;
            size_t goff = (size_t)(j0 + row) * (NKV * HD) + dq * 4;
            *(float4*)&Ks[row * APAD + dq * 4] = *(const float4*)&Kg[goff];
            *(float4*)&Vs[row * APAD + dq * 4] = *(const float4*)&Vg[goff];
        }
        __syncthreads();

        float s[8][4];
#pragma unroll
        for (int nt = 0; nt < 8; nt++)
#pragma unroll
            for (int c = 0; c < 4; c++) s[nt][c] = 0.0f;

#pragma unroll
        for (int ks = 0; ks < 8; ks++) {
            const int kk = ks * 8;
            const int qr = qbase + group;
            uint32_t a0 = to_tf32(Qs[qr * APAD + kk + tig]);
            uint32_t a1 = to_tf32(Qs[(qr + 8) * APAD + kk + tig]);
            uint32_t a2 = to_tf32(Qs[qr * APAD + kk + tig + 4]);
            uint32_t a3 = to_tf32(Qs[(qr + 8) * APAD + kk + tig + 4]);
#pragma unroll
            for (int nt = 0; nt < 8; nt++) {
                int key = nt * 8 + group;
                uint32_t b0 = to_tf32(Ks[key * APAD + kk + tig]);
                uint32_t b1 = to_tf32(Ks[key * APAD + kk + tig + 4]);
                mma_tf32(s[nt], a0, a1, a2, a3, b0, b1);
            }
        }

        const bool diag = (j0 == q0);
#pragma unroll
        for (int nt = 0; nt < 8; nt++) {
            int colg = j0 + nt * 8 + 2 * tig;
            s[nt][0] *= 0.125f; s[nt][1] *= 0.125f;
            s[nt][2] *= 0.125f; s[nt][3] *= 0.125f;
            if (diag) {
                if (colg > row0g) s[nt][0] = -1e30f;
                if (colg + 1 > row0g) s[nt][1] = -1e30f;
                if (colg > row1g) s[nt][2] = -1e30f;
                if (colg + 1 > row1g) s[nt][3] = -1e30f;
            }
        }

        float mx0 = -1e30f, mx1 = -1e30f;
#pragma unroll
        for (int nt = 0; nt < 8; nt++) {
            mx0 = fmaxf(mx0, fmaxf(s[nt][0], s[nt][1]));
            mx1 = fmaxf(mx1, fmaxf(s[nt][2], s[nt][3]));
        }
        mx0 = fmaxf(mx0, __shfl_xor_sync(0xffffffffu, mx0, 1));
        mx0 = fmaxf(mx0, __shfl_xor_sync(0xffffffffu, mx0, 2));
        mx1 = fmaxf(mx1, __shfl_xor_sync(0xffffffffu, mx1, 1));
        mx1 = fmaxf(mx1, __shfl_xor_sync(0xffffffffu, mx1, 2));

        float mn0 = fmaxf(mr0, mx0), mn1 = fmaxf(mr1, mx1);
        float corr0 = __expf(mr0 - mn0), corr1 = __expf(mr1 - mn1);
        float sum0 = 0.0f, sum1 = 0.0f;
#pragma unroll
        for (int nt = 0; nt < 8; nt++) {
            s[nt][0] = __expf(s[nt][0] - mn0);
            s[nt][1] = __expf(s[nt][1] - mn0);
            s[nt][2] = __expf(s[nt][2] - mn1);
            s[nt][3] = __expf(s[nt][3] - mn1);
            sum0 += s[nt][0] + s[nt][1];
            sum1 += s[nt][2] + s[nt][3];
        }
        sum0 += __shfl_xor_sync(0xffffffffu, sum0, 1);
        sum0 += __shfl_xor_sync(0xffffffffu, sum0, 2);
        sum1 += __shfl_xor_sync(0xffffffffu, sum1, 1);
        sum1 += __shfl_xor_sync(0xffffffffu, sum1, 2);
        lr0 = lr0 * corr0 + sum0;
        lr1 = lr1 * corr1 + sum1;
        mr0 = mn0; mr1 = mn1;

#pragma unroll
        for (int nt = 0; nt < 8; nt++) {
            o[nt][0] *= corr0; o[nt][1] *= corr0;
            o[nt][2] *= corr1; o[nt][3] *= corr1;
        }

        {
            int r0 = qbase + group;
#pragma unroll
            for (int nt = 0; nt < 8; nt++) {
                int col = nt * 8 + 2 * tig;
                *(float2*)&Ps[r0 * APAD + col] = make_float2(s[nt][0], s[nt][1]);
                *(float2*)&Ps[(r0 + 8) * APAD + col] = make_float2(s[nt][2], s[nt][3]);
            }
        }
        __syncwarp();

#pragma unroll
        for (int ks = 0; ks < 8; ks++) {
            const int kk = ks * 8;
            const int r0 = qbase + group;
            uint32_t a0 = to_tf32(Ps[r0 * APAD + kk + tig]);
            uint32_t a1 = to_tf32(Ps[(r0 + 8) * APAD + kk + tig]);
            uint32_t a2 = to_tf32(Ps[r0 * APAD + kk + tig + 4]);
            uint32_t a3 = to_tf32(Ps[(r0 + 8) * APAD + kk + tig + 4]);
#pragma unroll
            for (int nt = 0; nt < 8; nt++) {
                int d = nt * 8 + group;
                uint32_t b0 = to_tf32(Vs[(kk + tig) * APAD + d]);
                uint32_t b1 = to_tf32(Vs[(kk + tig + 4) * APAD + d]);
                mma_tf32(o[nt], a0, a1, a2, a3, b0, b1);
            }
        }
    }

    float inv0 = 1.0f / lr0, inv1 = 1.0f / lr1;
    float* Ag = g_A + (size_t)b * TT * CC + h * HD;
#pragma unroll
    for (int nt = 0; nt < 8; nt++) {
        int col = nt * 8 + 2 * tig;
        *(float2*)&Ag[(size_t)(q0 + qbase + group) * CC + col] =
            make_float2(o[nt][0] * inv0, o[nt][1] * inv0);
        *(float2*)&Ag[(size_t)(q0 + qbase + group + 8) * CC + col] =
            make_float2(o[nt][2] * inv1, o[nt][3] * inv1);
    }
}

// ---------------------------------------------------------------------------
extern "C" void kernel_launch(void* const* d_in, const int* in_sizes, int n_in,
                              void* d_out, int out_size) {
    const float* x   = (const float*)d_in[0];
    const int*   pos = (const int*)d_in[1];
    const float* q_w = (const float*)d_in[2];
    const float* q_b = (const float*)d_in[3];
    const float* k_w = (const float*)d_in[4];
    const float* k_b = (const float*)d_in[5];
    const float* v_w = (const float*)d_in[6];
    const float* v_b = (const float*)d_in[7];
    const float* o_w = (const float*)d_in[8];
    const float* o_b = (const float*)d_in[9];
    float* out = (float*)d_out;

    float *Qp, *Kp, *Vp, *Ap;
    cudaGetSymbolAddress((void**)&Qp, g_Q);
    cudaGetSymbolAddress((void**)&Kp, g_K);
    cudaGetSymbolAddress((void**)&Vp, g_V);
    cudaGetSymbolAddress((void**)&Ap, g_A);
    __nv_bfloat16 *xhi, *xlo, *ahi, *alo, *wqh, *wql, *wkh, *wkl, *wvh, *wvl, *woh, *wol;
    cudaGetSymbolAddress((void**)&xhi, g_xhi);
    cudaGetSymbolAddress((void**)&xlo, g_xlo);
    cudaGetSymbolAddress((void**)&ahi, g_ahi);
    cudaGetSymbolAddress((void**)&alo, g_alo);
    cudaGetSymbolAddress((void**)&wqh, g_wq_hi);
    cudaGetSymbolAddress((void**)&wql, g_wq_lo);
    cudaGetSymbolAddress((void**)&wkh, g_wk_hi);
    cudaGetSymbolAddress((void**)&wkl, g_wk_lo);
    cudaGetSymbolAddress((void**)&wvh, g_wv_hi);
    cudaGetSymbolAddress((void**)&wvl, g_wv_lo);
    cudaGetSymbolAddress((void**)&woh, g_wo_hi);
    cudaGetSymbolAddress((void**)&wol, g_wo_lo);

    const int NKVD = NKV * HD;  // 256
    const int gemm_smem = 2 * STAGE_B;  // 81920
    cudaFuncSetAttribute(gemm_bf16x3, cudaFuncAttributeMaxDynamicSharedMemorySize,
                         gemm_smem);

    // Splits
    split_ew<<<(MM * CC / 2 + 255) / 256, 256>>>(x, xhi, xlo, MM * CC);
    split_T<<<dim3(CC / 32, CC / 32), dim3(32, 8)>>>(q_w, wqh, wql, CC, CC);
    split_T<<<dim3(NKVD / 32, CC / 32), dim3(32, 8)>>>(k_w, wkh, wkl, CC, NKVD);
    split_T<<<dim3(NKVD / 32, CC / 32), dim3(32, 8)>>>(v_w, wvh, wvl, CC, NKVD);
    split_T<<<dim3(CC / 32, CC / 32), dim3(32, 8)>>>(o_w, woh, wol, CC, CC);

    // QKV projections
    gemm_bf16x3<<<dim3(CC / GBN, MM / GBM), 256, gemm_smem>>>(
        xhi, xlo, wqh, wql, q_b, Qp, MM, CC, CC);
    gemm_bf16x3<<<dim3(NKVD / GBN, MM / GBM), 256, gemm_smem>>>(
        xhi, xlo, wkh, wkl, k_b, Kp, MM, NKVD, CC);
    gemm_bf16x3<<<dim3(NKVD / GBN, MM / GBM), 256, gemm_smem>>>(
        xhi, xlo, wvh, wvl, v_b, Vp, MM, NKVD, CC);

    // RoPE
    {
        int totQ = MM * NH;
        int totK = MM * NKV;
        rope_kernel<<<(totQ + 7) / 8, 256>>>(Qp, pos, NH, totQ);
        rope_kernel<<<(totK + 7) / 8, 256>>>(Kp, pos, NKV, totK);
    }

    // Attention
    {
        const int smem_bytes = 4 * 64 * APAD * (int)sizeof(float);
        cudaFuncSetAttribute(attn_mma_kernel,
                             cudaFuncAttributeMaxDynamicSharedMemorySize, smem_bytes);
        attn_mma_kernel<<<dim3(TT / 64, NH, BB), 128, smem_bytes>>>();
    }

    // Output projection
    split_ew<<<(MM * CC / 2 + 255) / 256, 256>>>(Ap, ahi, alo, MM * CC);
    gemm_bf16x3<<<dim3(CC / GBN, MM / GBM), 256, gemm_smem>>>(
        ahi, alo, woh, wol, o_b, out, MM, CC, CC);
}

// round 5
// speedup vs baseline: 2.5459x; 1.1108x over previous
#include <cuda_runtime.h>
#include <cuda_bf16.h>
#include <math.h>
#include <stdint.h>

// Shapes
#define BB 8
#define TT 1024
#define CC 768
#define NH 12
#define NKV 4
#define HD 64
#define REP 3
#define MM (BB * TT)   // 8192
#define NKVD (NKV * HD)

// Scratch (no allocations allowed)
__device__ float g_Q[MM * CC];
__device__ float g_K[MM * NKVD];
__device__ float g_V[MM * NKVD];

// bf16 split scratch
__device__ __nv_bfloat16 g_xhi[MM * CC], g_xlo[MM * CC];
__device__ __nv_bfloat16 g_ahi[MM * CC], g_alo[MM * CC];
__device__ __nv_bfloat16 g_wq_hi[CC * CC], g_wq_lo[CC * CC];
__device__ __nv_bfloat16 g_wk_hi[NKVD * CC], g_wk_lo[NKVD * CC];
__device__ __nv_bfloat16 g_wv_hi[NKVD * CC], g_wv_lo[NKVD * CC];
__device__ __nv_bfloat16 g_wo_hi[CC * CC], g_wo_lo[CC * CC];

// ---------------------------------------------------------------------------
// helpers
// ---------------------------------------------------------------------------
__device__ __forceinline__ uint32_t to_tf32(float a) {
    uint32_t r;
    asm("cvt.rna.tf32.f32 %0, %1;" : "=r"(r) : "f"(a));
    return r;
}
__device__ __forceinline__ void mma_tf32(float c[4], uint32_t a0, uint32_t a1,
                                         uint32_t a2, uint32_t a3,
                                         uint32_t b0, uint32_t b1) {
    asm volatile(
        "mma.sync.aligned.m16n8k8.row.col.f32.tf32.tf32.f32 "
        "{%0,%1,%2,%3}, {%4,%5,%6,%7}, {%8,%9}, {%0,%1,%2,%3};"
        : "+f"(c[0]), "+f"(c[1]), "+f"(c[2]), "+f"(c[3])
        : "r"(a0), "r"(a1), "r"(a2), "r"(a3), "r"(b0), "r"(b1));
}
__device__ __forceinline__ void mma_bf16(float c[4], const uint32_t a[4],
                                         const uint32_t b[2]) {
    asm volatile(
        "mma.sync.aligned.m16n8k16.row.col.f32.bf16.bf16.f32 "
        "{%0,%1,%2,%3}, {%4,%5,%6,%7}, {%8,%9}, {%0,%1,%2,%3};"
        : "+f"(c[0]), "+f"(c[1]), "+f"(c[2]), "+f"(c[3])
        : "r"(a[0]), "r"(a[1]), "r"(a[2]), "r"(a[3]), "r"(b[0]), "r"(b[1]));
}
__device__ __forceinline__ void ldsm4(uint32_t r[4], uint32_t addr) {
    asm volatile("ldmatrix.sync.aligned.m8n8.x4.shared.b16 {%0,%1,%2,%3}, [%4];"
                 : "=r"(r[0]), "=r"(r[1]), "=r"(r[2]), "=r"(r[3]) : "r"(addr));
}
__device__ __forceinline__ void cp16(void* dst_smem, const void* src) {
    uint32_t d = (uint32_t)__cvta_generic_to_shared(dst_smem);
    asm volatile("cp.async.cg.shared.global [%0], [%1], 16;" :: "r"(d), "l"(src));
}
__device__ __forceinline__ void split_one(float v, __nv_bfloat16& h, __nv_bfloat16& l) {
    h = __float2bfloat16_rn(v);
    l = __float2bfloat16_rn(v - __bfloat162float(h));
}

// ---------------------------------------------------------------------------
// Elementwise split: fp32 -> hi/lo bf16.
// ---------------------------------------------------------------------------
__global__ void split_ew(const float* __restrict__ in, __nv_bfloat16* __restrict__ hi,
                         __nv_bfloat16* __restrict__ lo, int n) {
    int i = (blockIdx.x * blockDim.x + threadIdx.x) * 2;
    if (i >= n) return;
    float2 v = *(const float2*)&in[i];
    __nv_bfloat16 h0, l0, h1, l1;
    split_one(v.x, h0, l0);
    split_one(v.y, h1, l1);
    *(__nv_bfloat162*)&hi[i] = __nv_bfloat162(h0, h1);
    *(__nv_bfloat162*)&lo[i] = __nv_bfloat162(l0, l1);
}

// ---------------------------------------------------------------------------
// Transpose + split: W[K][N] fp32 -> hi/lo[N][K] bf16. 32x32 tiles.
// ---------------------------------------------------------------------------
__global__ void split_T(const float* __restrict__ W, __nv_bfloat16* __restrict__ hi,
                        __nv_bfloat16* __restrict__ lo, int K, int N) {
    __shared__ float t[32][33];
    const int n0 = blockIdx.x * 32, k0 = blockIdx.y * 32;
    const int tx = threadIdx.x, ty = threadIdx.y;
#pragma unroll
    for (int j = 0; j < 4; j++)
        t[ty + j * 8][tx] = W[(size_t)(k0 + ty + j * 8) * N + n0 + tx];
    __syncthreads();
#pragma unroll
    for (int j = 0; j < 4; j++) {
        int r = ty + j * 8;
        float v = t[tx][r];
        __nv_bfloat16 h, l;
        split_one(v, h, l);
        hi[(size_t)(n0 + r) * K + k0 + tx] = h;
        lo[(size_t)(n0 + r) * K + k0 + tx] = l;
    }
}

// ---------------------------------------------------------------------------
// bf16x3 GEMM with ldmatrix fragments.
// Block 128x128, BK=32, 256 threads, warp tile 64x32, cp.async double buffer.
// ---------------------------------------------------------------------------
#define GBM 128
#define GBN 128
#define GBK 32
#define STAGE_B 40960
#define ARR_B 10240

__global__ __launch_bounds__(256)
void gemm_bf16x3(const __nv_bfloat16* __restrict__ Ah, const __nv_bfloat16* __restrict__ Al,
                 const __nv_bfloat16* __restrict__ Bh, const __nv_bfloat16* __restrict__ Bl,
                 const float* __restrict__ bias, float* __restrict__ C,
                 int M, int N, int K, int round_out) {
    extern __shared__ char smem_raw[];
    const uint32_t smem_sh = (uint32_t)__cvta_generic_to_shared(smem_raw);

    const int tid = threadIdx.x;
    const int wid = tid >> 5;
    const int lane = tid & 31;
    const int group = lane >> 2;
    const int tig = lane & 3;
    const int warpm = wid & 1;
    const int warpn = wid >> 1;
    const int m0 = blockIdx.y * GBM;
    const int n0 = blockIdx.x * GBN;

    const __nv_bfloat16* gsrc[4] = {Ah, Al, Bh, Bl};

    auto load_stage = [&](int stage, int kt) {
        char* sbase = smem_raw + stage * STAGE_B;
#pragma unroll
        for (int i = 0; i < 8; i++) {
            int cid = tid + i * 256;
            int arr = cid >> 9;
            int within = cid & 511;
            int row = within >> 2;
            int c = within & 3;
            int grow = (arr < 2) ? (m0 + row) : (n0 + row);
            const __nv_bfloat16* src = gsrc[arr] + (size_t)grow * K + kt + c * 8;
            cp16(sbase + arr * ARR_B + row * 80 + c * 16, src);
        }
        asm volatile("cp.async.commit_group;");
    };

    float acc[4][4][4];
#pragma unroll
    for (int mt = 0; mt < 4; mt++)
#pragma unroll
        for (int nt = 0; nt < 4; nt++)
#pragma unroll
            for (int c = 0; c < 4; c++) acc[mt][nt][c] = 0.0f;

    const int ntiles = K / GBK;
    load_stage(0, 0);

    for (int t = 0; t < ntiles; t++) {
        if (t + 1 < ntiles) {
            load_stage((t + 1) & 1, (t + 1) * GBK);
            asm volatile("cp.async.wait_group 1;");
        } else {
            asm volatile("cp.async.wait_group 0;");
        }
        __syncthreads();

        const uint32_t sb = smem_sh + (t & 1) * STAGE_B;
#pragma unroll
        for (int s = 0; s < 2; s++) {
            const int soff = s * 32;
            uint32_t ahi[4][4], alo[4][4], bph[2][4], bpl[2][4];
            uint32_t aaddr = sb + (uint32_t)(warpm * 64 + (lane & 15)) * 80 + soff
                             + ((lane >> 4) << 4);
#pragma unroll
            for (int mt = 0; mt < 4; mt++) {
                ldsm4(ahi[mt], aaddr + mt * 16 * 80);
                ldsm4(alo[mt], aaddr + ARR_B + mt * 16 * 80);
            }
            uint32_t baddr = sb + 2 * ARR_B
                             + (uint32_t)(warpn * 32 + ((lane >> 4) << 3) + (lane & 7)) * 80
                             + soff + (((lane >> 3) & 1) << 4);
            ldsm4(bph[0], baddr);
            ldsm4(bph[1], baddr + 16 * 80);
            ldsm4(bpl[0], baddr + ARR_B);
            ldsm4(bpl[1], baddr + ARR_B + 16 * 80);

#pragma unroll
            for (int mt = 0; mt < 4; mt++)
#pragma unroll
                for (int nt = 0; nt < 4; nt++) {
                    const uint32_t* bh = &bph[nt >> 1][(nt & 1) * 2];
                    const uint32_t* bl = &bpl[nt >> 1][(nt & 1) * 2];
                    mma_bf16(acc[mt][nt], ahi[mt], bh);
                    mma_bf16(acc[mt][nt], alo[mt], bh);
                    mma_bf16(acc[mt][nt], ahi[mt], bl);
                }
        }
        __syncthreads();
    }

    // Epilogue
#pragma unroll
    for (int mt = 0; mt < 4; mt++) {
        int r = m0 + warpm * 64 + mt * 16 + group;
#pragma unroll
        for (int nt = 0; nt < 4; nt++) {
            int col = n0 + warpn * 32 + nt * 8 + 2 * tig;
            float b0v = bias[col], b1v = bias[col + 1];
            float v0 = acc[mt][nt][0] + b0v, v1 = acc[mt][nt][1] + b1v;
            float v2 = acc[mt][nt][2] + b0v, v3 = acc[mt][nt][3] + b1v;
            if (round_out) {
                v0 = __uint_as_float(to_tf32(v0));
                v1 = __uint_as_float(to_tf32(v1));
                v2 = __uint_as_float(to_tf32(v2));
                v3 = __uint_as_float(to_tf32(v3));
            }
            *(float2*)&C[(size_t)r * N + col] = make_float2(v0, v1);
            *(float2*)&C[(size_t)(r + 8) * N + col] = make_float2(v2, v3);
        }
    }
}

// ---------------------------------------------------------------------------
// RoPE (interleaved rotate_half), in place; rounds outputs to tf32 values.
// ---------------------------------------------------------------------------
__global__ void rope_kernel(float* __restrict__ buf, const int* __restrict__ pos,
                            int nHeads, int total) {
    __shared__ float sv[8][64];
    const int warp = threadIdx.x >> 5;
    const int lane = threadIdx.x & 31;
    const int vec = blockIdx.x * 8 + warp;
    if (vec >= total) return;

    const int h = vec % nHeads;
    const int bt = vec / nHeads;
    const int t = bt % TT;
    float* p = buf + (size_t)bt * (nHeads * HD) + h * HD;

    sv[warp][lane] = p[lane];
    sv[warp][lane + 32] = p[lane + 32];
    __syncwarp();

    const float po = (float)pos[t];
    const float freq = exp2f(-(float)lane * (13.287712379549449f / 32.0f));
    float sn, cs;
    sincosf(po * freq, &sn, &cs);

    const int j = lane;
    const float xj = sv[warp][j];
    const float xj32 = sv[warp][j + 32];
    const float rot_lo = (j & 1) ? -sv[warp][47 + ((j + 1) >> 1)]
                                 : -sv[warp][16 + (j >> 1)];
    const float rot_hi = (j & 1) ? sv[warp][32 + ((j - 1) >> 1)]
                                 : sv[warp][j >> 1];
    p[j] = __uint_as_float(to_tf32(xj * cs + rot_lo * sn));
    p[j + 32] = __uint_as_float(to_tf32(xj32 * cs + rot_hi * sn));
}

// ---------------------------------------------------------------------------
// Flash attention, tf32 MMA. 128-query blocks, 4 warps x 32 rows.
// Q/K/V in global are already tf32-valued -> raw bit loads, no CVT.
// K/V tiles double-buffered via cp.async. Epilogue fuses bf16 hi/lo split.
// ---------------------------------------------------------------------------
#define AW 68
__global__ __launch_bounds__(128)
void attn_mma_kernel() {
    extern __shared__ float sm[];
    float* Qs = sm;                       // 128*68
    float* Ks = Qs + 128 * AW;            // 2 stages of 64*68
    float* Vs = Ks + 2 * 64 * AW;         // 2 stages of 64*68
    float* Ps = Vs + 2 * 64 * AW;         // 128*68

    const int tid = threadIdx.x;
    const int wid = tid >> 5;
    const int lane = tid & 31;
    const int group = lane >> 2;
    const int tig = lane & 3;
    const int q0 = blockIdx.x * 128;
    const int h = blockIdx.y;
    const int b = blockIdx.z;
    const int kvh = h / REP;
    const int qbase = wid * 32;

    const float* Qg = g_Q + (size_t)b * TT * CC + h * HD;
    const float* Kg = g_K + (size_t)b * TT * NKVD + kvh * HD;
    const float* Vg = g_V + (size_t)b * TT * NKVD + kvh * HD;

    // Load Q tile (128 x 64)
#pragma unroll
    for (int r = 0; r < 16; r++) {
        int idx = tid + r * 128;
        int row = idx >> 4, dq = idx & 15;
        float4 v = *(const float4*)&Qg[(size_t)(q0 + row) * CC + dq * 4];
        *(float4*)&Qs[row * AW + dq * 4] = v;
    }

    auto issue_kv = [&](int stage, int j0) {
        float* Kd = Ks + stage * 64 * AW;
        float* Vd = Vs + stage * 64 * AW;
#pragma unroll
        for (int i = 0; i < 16; i++) {
            int cid = tid + i * 128;          // 0..2047
            int isV = cid >> 10;
            int within = cid & 1023;
            int row = within >> 4;            // 0..63
            int c = within & 15;
            const float* src = (isV ? Vg : Kg) + (size_t)(j0 + row) * NKVD + c * 4;
            float* dst = (isV ? Vd : Kd) + row * AW + c * 4;
            cp16(dst, src);
        }
        asm volatile("cp.async.commit_group;");
    };

    issue_kv(0, 0);

    float mr[2][2] = {{-1e30f, -1e30f}, {-1e30f, -1e30f}};
    float lr[2][2] = {{0.0f, 0.0f}, {0.0f, 0.0f}};
    float o[2][8][4];
#pragma unroll
    for (int mt = 0; mt < 2; mt++)
#pragma unroll
        for (int nt = 0; nt < 8; nt++)
#pragma unroll
            for (int c = 0; c < 4; c++) o[mt][nt][c] = 0.0f;

    const uint32_t* Qu = (const uint32_t*)Qs;
    uint32_t* Pu = (uint32_t*)Ps;
    const int jmax = q0 + 64;

    int stage = 0;
    for (int j0 = 0; j0 <= jmax; j0 += 64, stage ^= 1) {
        asm volatile("cp.async.wait_group 0;");
        __syncthreads();
        if (j0 + 64 <= jmax) issue_kv(stage ^ 1, j0 + 64);

        const uint32_t* Ku = (const uint32_t*)(Ks + stage * 64 * AW);
        const uint32_t* Vu = (const uint32_t*)(Vs + stage * 64 * AW);

        // ---- S = Q K^T ----
        float s[2][8][4];
#pragma unroll
        for (int mt = 0; mt < 2; mt++)
#pragma unroll
            for (int nt = 0; nt < 8; nt++)
#pragma unroll
                for (int c = 0; c < 4; c++) s[mt][nt][c] = 0.0f;

#pragma unroll
        for (int ks = 0; ks < 8; ks++) {
            const int kk = ks * 8;
            uint32_t a[2][4];
#pragma unroll
            for (int mt = 0; mt < 2; mt++) {
                int r = qbase + mt * 16 + group;
                a[mt][0] = Qu[r * AW + kk + tig];
                a[mt][1] = Qu[(r + 8) * AW + kk + tig];
                a[mt][2] = Qu[r * AW + kk + tig + 4];
                a[mt][3] = Qu[(r + 8) * AW + kk + tig + 4];
            }
#pragma unroll
            for (int nt = 0; nt < 8; nt++) {
                int key = nt * 8 + group;
                uint32_t b0 = Ku[key * AW + kk + tig];
                uint32_t b1 = Ku[key * AW + kk + tig + 4];
                mma_tf32(s[0][nt], a[0][0], a[0][1], a[0][2], a[0][3], b0, b1);
                mma_tf32(s[1][nt], a[1][0], a[1][1], a[1][2], a[1][3], b0, b1);
            }
        }

        // ---- scale + causal mask + online softmax per mt ----
        const bool diag = (j0 + 64 > q0);
#pragma unroll
        for (int mt = 0; mt < 2; mt++) {
            const int row0g = q0 + qbase + mt * 16 + group;
            const int row1g = row0g + 8;
#pragma unroll
            for (int nt = 0; nt < 8; nt++) {
                int colg = j0 + nt * 8 + 2 * tig;
                s[mt][nt][0] *= 0.125f; s[mt][nt][1] *= 0.125f;
                s[mt][nt][2] *= 0.125f; s[mt][nt][3] *= 0.125f;
                if (diag) {
                    if (colg > row0g) s[mt][nt][0] = -1e30f;
                    if (colg + 1 > row0g) s[mt][nt][1] = -1e30f;
                    if (colg > row1g) s[mt][nt][2] = -1e30f;
                    if (colg + 1 > row1g) s[mt][nt][3] = -1e30f;
                }
            }
            float mx0 = -1e30f, mx1 = -1e30f;
#pragma unroll
            for (int nt = 0; nt < 8; nt++) {
                mx0 = fmaxf(mx0, fmaxf(s[mt][nt][0], s[mt][nt][1]));
                mx1 = fmaxf(mx1, fmaxf(s[mt][nt][2], s[mt][nt][3]));
            }
            mx0 = fmaxf(mx0, __shfl_xor_sync(0xffffffffu, mx0, 1));
            mx0 = fmaxf(mx0, __shfl_xor_sync(0xffffffffu, mx0, 2));
            mx1 = fmaxf(mx1, __shfl_xor_sync(0xffffffffu, mx1, 1));
            mx1 = fmaxf(mx1, __shfl_xor_sync(0xffffffffu, mx1, 2));

            float mn0 = fmaxf(mr[mt][0], mx0), mn1 = fmaxf(mr[mt][1], mx1);
            float corr0 = __expf(mr[mt][0] - mn0), corr1 = __expf(mr[mt][1] - mn1);
            float sum0 = 0.0f, sum1 = 0.0f;
#pragma unroll
            for (int nt = 0; nt < 8; nt++) {
                s[mt][nt][0] = __expf(s[mt][nt][0] - mn0);
                s[mt][nt][1] = __expf(s[mt][nt][1] - mn0);
                s[mt][nt][2] = __expf(s[mt][nt][2] - mn1);
                s[mt][nt][3] = __expf(s[mt][nt][3] - mn1);
                sum0 += s[mt][nt][0] + s[mt][nt][1];
                sum1 += s[mt][nt][2] + s[mt][nt][3];
            }
            sum0 += __shfl_xor_sync(0xffffffffu, sum0, 1);
            sum0 += __shfl_xor_sync(0xffffffffu, sum0, 2);
            sum1 += __shfl_xor_sync(0xffffffffu, sum1, 1);
            sum1 += __shfl_xor_sync(0xffffffffu, sum1, 2);
            lr[mt][0] = lr[mt][0] * corr0 + sum0;
            lr[mt][1] = lr[mt][1] * corr1 + sum1;
            mr[mt][0] = mn0; mr[mt][1] = mn1;

#pragma unroll
            for (int nt = 0; nt < 8; nt++) {
                o[mt][nt][0] *= corr0; o[mt][nt][1] *= corr0;
                o[mt][nt][2] *= corr1; o[mt][nt][3] *= corr1;
            }

            // store P (tf32 bits) to per-warp smem slice
            int r0 = qbase + mt * 16 + group;
#pragma unroll
            for (int nt = 0; nt < 8; nt++) {
                int col = nt * 8 + 2 * tig;
                Pu[r0 * AW + col] = to_tf32(s[mt][nt][0]);
                Pu[r0 * AW + col + 1] = to_tf32(s[mt][nt][1]);
                Pu[(r0 + 8) * AW + col] = to_tf32(s[mt][nt][2]);
                Pu[(r0 + 8) * AW + col + 1] = to_tf32(s[mt][nt][3]);
            }
        }
        __syncwarp();

        // ---- O += P V ----
#pragma unroll
        for (int ks = 0; ks < 8; ks++) {
            const int kk = ks * 8;
            uint32_t a[2][4];
#pragma unroll
            for (int mt = 0; mt < 2; mt++) {
                int r = qbase + mt * 16 + group;
                a[mt][0] = Pu[r * AW + kk + tig];
                a[mt][1] = Pu[(r + 8) * AW + kk + tig];
                a[mt][2] = Pu[r * AW + kk + tig + 4];
                a[mt][3] = Pu[(r + 8) * AW + kk + tig + 4];
            }
#pragma unroll
            for (int nt = 0; nt < 8; nt++) {
                int d = nt * 8 + group;
                uint32_t b0 = Vu[(kk + tig) * AW + d];
                uint32_t b1 = Vu[(kk + tig + 4) * AW + d];
                mma_tf32(o[0][nt], a[0][0], a[0][1], a[0][2], a[0][3], b0, b1);
                mma_tf32(o[1][nt], a[1][0], a[1][1], a[1][2], a[1][3], b0, b1);
            }
        }
    }

    // Epilogue: normalize, split to bf16 hi/lo, write directly
#pragma unroll
    for (int mt = 0; mt < 2; mt++) {
        float inv0 = 1.0f / lr[mt][0], inv1 = 1.0f / lr[mt][1];
        size_t row0 = (size_t)(b * TT + q0 + qbase + mt * 16 + group) * CC + h * HD;
        size_t row1 = row0 + 8 * CC;
#pragma unroll
        for (int nt = 0; nt < 8; nt++) {
            int col = nt * 8 + 2 * tig;
            float v0 = o[mt][nt][0] * inv0, v1 = o[mt][nt][1] * inv0;
            float v2 = o[mt][nt][2] * inv1, v3 = o[mt][nt][3] * inv1;
            __nv_bfloat16 h0, l0, h1, l1, h2, l2, h3, l3;
            split_one(v0, h0, l0); split_one(v1, h1, l1);
            split_one(v2, h2, l2); split_one(v3, h3, l3);
            *(__nv_bfloat162*)&g_ahi[row0 + col] = __nv_bfloat162(h0, h1);
            *(__nv_bfloat162*)&g_alo[row0 + col] = __nv_bfloat162(l0, l1);
            *(__nv_bfloat162*)&g_ahi[row1 + col] = __nv_bfloat162(h2, h3);
            *(__nv_bfloat162*)&g_alo[row1 + col] = __nv_bfloat162(l2, l3);
        }
    }
}

// ---------------------------------------------------------------------------
extern "C" void kernel_launch(void* const* d_in, const int* in_sizes, int n_in,
                              void* d_out, int out_size) {
    const float* x   = (const float*)d_in[0];
    const int*   pos = (const int*)d_in[1];
    const float* q_w = (const float*)d_in[2];
    const float* q_b = (const float*)d_in[3];
    const float* k_w = (const float*)d_in[4];
    const float* k_b = (const float*)d_in[5];
    const float* v_w = (const float*)d_in[6];
    const float* v_b = (const float*)d_in[7];
    const float* o_w = (const float*)d_in[8];
    const float* o_b = (const float*)d_in[9];
    float* out = (float*)d_out;

    float *Qp, *Kp, *Vp;
    cudaGetSymbolAddress((void**)&Qp, g_Q);
    cudaGetSymbolAddress((void**)&Kp, g_K);
    cudaGetSymbolAddress((void**)&Vp, g_V);
    __nv_bfloat16 *xhi, *xlo, *ahi, *alo, *wqh, *wql, *wkh, *wkl, *wvh, *wvl, *woh, *wol;
    cudaGetSymbolAddress((void**)&xhi, g_xhi);
    cudaGetSymbolAddress((void**)&xlo, g_xlo);
    cudaGetSymbolAddress((void**)&ahi, g_ahi);
    cudaGetSymbolAddress((void**)&alo, g_alo);
    cudaGetSymbolAddress((void**)&wqh, g_wq_hi);
    cudaGetSymbolAddress((void**)&wql, g_wq_lo);
    cudaGetSymbolAddress((void**)&wkh, g_wk_hi);
    cudaGetSymbolAddress((void**)&wkl, g_wk_lo);
    cudaGetSymbolAddress((void**)&wvh, g_wv_hi);
    cudaGetSymbolAddress((void**)&wvl, g_wv_lo);
    cudaGetSymbolAddress((void**)&woh, g_wo_hi);
    cudaGetSymbolAddress((void**)&wol, g_wo_lo);

    const int gemm_smem = 2 * STAGE_B;  // 81920
    cudaFuncSetAttribute(gemm_bf16x3, cudaFuncAttributeMaxDynamicSharedMemorySize,
                         gemm_smem);

    // Splits
    split_ew<<<(MM * CC / 2 + 255) / 256, 256>>>(x, xhi, xlo, MM * CC);
    split_T<<<dim3(CC / 32, CC / 32), dim3(32, 8)>>>(q_w, wqh, wql, CC, CC);
    split_T<<<dim3(NKVD / 32, CC / 32), dim3(32, 8)>>>(k_w, wkh, wkl, CC, NKVD);
    split_T<<<dim3(NKVD / 32, CC / 32), dim3(32, 8)>>>(v_w, wvh, wvl, CC, NKVD);
    split_T<<<dim3(CC / 32, CC / 32), dim3(32, 8)>>>(o_w, woh, wol, CC, CC);

    // QKV projections (V rounded to tf32 in epilogue; Q,K rounded by rope)
    gemm_bf16x3<<<dim3(CC / GBN, MM / GBM), 256, gemm_smem>>>(
        xhi, xlo, wqh, wql, q_b, Qp, MM, CC, CC, 0);
    gemm_bf16x3<<<dim3(NKVD / GBN, MM / GBM), 256, gemm_smem>>>(
        xhi, xlo, wkh, wkl, k_b, Kp, MM, NKVD, CC, 0);
    gemm_bf16x3<<<dim3(NKVD / GBN, MM / GBM), 256, gemm_smem>>>(
        xhi, xlo, wvh, wvl, v_b, Vp, MM, NKVD, CC, 1);

    // RoPE (rounds outputs to tf32 values)
    {
        int totQ = MM * NH;
        int totK = MM * NKV;
        rope_kernel<<<(totQ + 7) / 8, 256>>>(Qp, pos, NH, totQ);
        rope_kernel<<<(totK + 7) / 8, 256>>>(Kp, pos, NKV, totK);
    }

    // Attention (writes bf16 hi/lo split directly)
    {
        const int smem_bytes = (2 * 128 * AW + 4 * 64 * AW) * (int)sizeof(float); // 139264
        cudaFuncSetAttribute(attn_mma_kernel,
                             cudaFuncAttributeMaxDynamicSharedMemorySize, smem_bytes);
        attn_mma_kernel<<<dim3(TT / 128, NH, BB), 128, smem_bytes>>>();
    }

    // Output projection -> d_out
    gemm_bf16x3<<<dim3(CC / GBN, MM / GBM), 256, gemm_smem>>>(
        ahi, alo, woh, wol, o_b, out, MM, CC, CC, 0);
}

// round 15
// speedup vs baseline: 2.7425x; 1.0772x over previous
#include <cuda_runtime.h>
#include <cuda_bf16.h>
#include <math.h>
#include <stdint.h>

// Shapes
#define BB 8
#define TT 1024
#define CC 768
#define NH 12
#define NKV 4
#define HD 64
#define REP 3
#define MM (BB * TT)   // 8192
#define NKVD (NKV * HD)
#define QKVW 1280      // 768 Q + 256 K + 256 V

// Scratch (no allocations allowed)
__device__ float g_QKV[MM * QKVW];     // [b*T+t][ Q(768) | K(256) | V(256) ]

// bf16 split scratch
__device__ __nv_bfloat16 g_xhi[MM * CC], g_xlo[MM * CC];
__device__ __nv_bfloat16 g_ahi[MM * CC], g_alo[MM * CC];
__device__ __nv_bfloat16 g_wqkv_hi[QKVW * CC], g_wqkv_lo[QKVW * CC];  // [n][k]
__device__ __nv_bfloat16 g_wo_hi[CC * CC], g_wo_lo[CC * CC];
__device__ float g_bqkv[QKVW];

// ---------------------------------------------------------------------------
// helpers
// ---------------------------------------------------------------------------
__device__ __forceinline__ uint32_t to_tf32(float a) {
    uint32_t r;
    asm("cvt.rna.tf32.f32 %0, %1;" : "=r"(r) : "f"(a));
    return r;
}
__device__ __forceinline__ void mma_tf32(float c[4], uint32_t a0, uint32_t a1,
                                         uint32_t a2, uint32_t a3,
                                         uint32_t b0, uint32_t b1) {
    asm volatile(
        "mma.sync.aligned.m16n8k8.row.col.f32.tf32.tf32.f32 "
        "{%0,%1,%2,%3}, {%4,%5,%6,%7}, {%8,%9}, {%0,%1,%2,%3};"
        : "+f"(c[0]), "+f"(c[1]), "+f"(c[2]), "+f"(c[3])
        : "r"(a0), "r"(a1), "r"(a2), "r"(a3), "r"(b0), "r"(b1));
}
__device__ __forceinline__ void mma_bf16(float c[4], const uint32_t a[4],
                                         const uint32_t b[2]) {
    asm volatile(
        "mma.sync.aligned.m16n8k16.row.col.f32.bf16.bf16.f32 "
        "{%0,%1,%2,%3}, {%4,%5,%6,%7}, {%8,%9}, {%0,%1,%2,%3};"
        : "+f"(c[0]), "+f"(c[1]), "+f"(c[2]), "+f"(c[3])
        : "r"(a[0]), "r"(a[1]), "r"(a[2]), "r"(a[3]), "r"(b[0]), "r"(b[1]));
}
__device__ __forceinline__ void ldsm4(uint32_t r[4], uint32_t addr) {
    asm volatile("ldmatrix.sync.aligned.m8n8.x4.shared.b16 {%0,%1,%2,%3}, [%4];"
                 : "=r"(r[0]), "=r"(r[1]), "=r"(r[2]), "=r"(r[3]) : "r"(addr));
}
__device__ __forceinline__ void cp16(void* dst_smem, const void* src) {
    uint32_t d = (uint32_t)__cvta_generic_to_shared(dst_smem);
    asm volatile("cp.async.cg.shared.global [%0], [%1], 16;" :: "r"(d), "l"(src));
}
__device__ __forceinline__ void split_one(float v, __nv_bfloat16& h, __nv_bfloat16& l) {
    h = __float2bfloat16_rn(v);
    l = __float2bfloat16_rn(v - __bfloat162float(h));
}

// ---------------------------------------------------------------------------
// Elementwise split: fp32 -> hi/lo bf16.
// ---------------------------------------------------------------------------
__global__ void split_ew(const float* __restrict__ in, __nv_bfloat16* __restrict__ hi,
                         __nv_bfloat16* __restrict__ lo, int n) {
    int i = (blockIdx.x * blockDim.x + threadIdx.x) * 2;
    if (i >= n) return;
    float2 v = *(const float2*)&in[i];
    __nv_bfloat16 h0, l0, h1, l1;
    split_one(v.x, h0, l0);
    split_one(v.y, h1, l1);
    *(__nv_bfloat162*)&hi[i] = __nv_bfloat162(h0, h1);
    *(__nv_bfloat162*)&lo[i] = __nv_bfloat162(l0, l1);
}

// ---------------------------------------------------------------------------
// Transpose + split: W[K][N] fp32 -> hi/lo[N][K] bf16. 32x32 tiles.
// ---------------------------------------------------------------------------
__global__ void split_T(const float* __restrict__ W, __nv_bfloat16* __restrict__ hi,
                        __nv_bfloat16* __restrict__ lo, int K, int N) {
    __shared__ float t[32][33];
    const int n0 = blockIdx.x * 32, k0 = blockIdx.y * 32;
    const int tx = threadIdx.x, ty = threadIdx.y;
#pragma unroll
    for (int j = 0; j < 4; j++)
        t[ty + j * 8][tx] = W[(size_t)(k0 + ty + j * 8) * N + n0 + tx];
    __syncthreads();
#pragma unroll
    for (int j = 0; j < 4; j++) {
        int r = ty + j * 8;
        float v = t[tx][r];
        __nv_bfloat16 h, l;
        split_one(v, h, l);
        hi[(size_t)(n0 + r) * K + k0 + tx] = h;
        lo[(size_t)(n0 + r) * K + k0 + tx] = l;
    }
}

// ---------------------------------------------------------------------------
// Bias concat: [ q_b | k_b | v_b ] -> g_bqkv
// ---------------------------------------------------------------------------
__global__ void concat_bias(const float* __restrict__ qb, const float* __restrict__ kb,
                            const float* __restrict__ vb) {
    int i = blockIdx.x * blockDim.x + threadIdx.x;
    if (i >= QKVW) return;
    float v;
    if (i < CC) v = qb[i];
    else if (i < CC + NKVD) v = kb[i - CC];
    else v = vb[i - CC - NKVD];
    g_bqkv[i] = v;
}

// ---------------------------------------------------------------------------
// bf16x3 GEMM with ldmatrix fragments.
// Block 128x128, BK=32, 256 threads, warp tile 64x32, cp.async double buffer.
// Columns >= round_from are rounded to tf32 values in the epilogue.
// ---------------------------------------------------------------------------
#define GBM 128
#define GBN 128
#define GBK 32
#define STAGE_B 40960
#define ARR_B 10240

__global__ __launch_bounds__(256)
void gemm_bf16x3(const __nv_bfloat16* __restrict__ Ah, const __nv_bfloat16* __restrict__ Al,
                 const __nv_bfloat16* __restrict__ Bh, const __nv_bfloat16* __restrict__ Bl,
                 const float* __restrict__ bias, float* __restrict__ C,
                 int M, int N, int K, int round_from) {
    extern __shared__ char smem_raw[];
    const uint32_t smem_sh = (uint32_t)__cvta_generic_to_shared(smem_raw);

    const int tid = threadIdx.x;
    const int wid = tid >> 5;
    const int lane = tid & 31;
    const int group = lane >> 2;
    const int tig = lane & 3;
    const int warpm = wid & 1;
    const int warpn = wid >> 1;
    const int m0 = blockIdx.y * GBM;
    const int n0 = blockIdx.x * GBN;

    const __nv_bfloat16* gsrc[4] = {Ah, Al, Bh, Bl};

    auto load_stage = [&](int stage, int kt) {
        char* sbase = smem_raw + stage * STAGE_B;
#pragma unroll
        for (int i = 0; i < 8; i++) {
            int cid = tid + i * 256;
            int arr = cid >> 9;
            int within = cid & 511;
            int row = within >> 2;
            int c = within & 3;
            int grow = (arr < 2) ? (m0 + row) : (n0 + row);
            const __nv_bfloat16* src = gsrc[arr] + (size_t)grow * K + kt + c * 8;
            cp16(sbase + arr * ARR_B + row * 80 + c * 16, src);
        }
        asm volatile("cp.async.commit_group;");
    };

    float acc[4][4][4];
#pragma unroll
    for (int mt = 0; mt < 4; mt++)
#pragma unroll
        for (int nt = 0; nt < 4; nt++)
#pragma unroll
            for (int c = 0; c < 4; c++) acc[mt][nt][c] = 0.0f;

    const int ntiles = K / GBK;
    load_stage(0, 0);

    for (int t = 0; t < ntiles; t++) {
        if (t + 1 < ntiles) {
            load_stage((t + 1) & 1, (t + 1) * GBK);
            asm volatile("cp.async.wait_group 1;");
        } else {
            asm volatile("cp.async.wait_group 0;");
        }
        __syncthreads();

        const uint32_t sb = smem_sh + (t & 1) * STAGE_B;
#pragma unroll
        for (int s = 0; s < 2; s++) {
            const int soff = s * 32;
            uint32_t ahi[4][4], alo[4][4], bph[2][4], bpl[2][4];
            uint32_t aaddr = sb + (uint32_t)(warpm * 64 + (lane & 15)) * 80 + soff
                             + ((lane >> 4) << 4);
#pragma unroll
            for (int mt = 0; mt < 4; mt++) {
                ldsm4(ahi[mt], aaddr + mt * 16 * 80);
                ldsm4(alo[mt], aaddr + ARR_B + mt * 16 * 80);
            }
            uint32_t baddr = sb + 2 * ARR_B
                             + (uint32_t)(warpn * 32 + ((lane >> 4) << 3) + (lane & 7)) * 80
                             + soff + (((lane >> 3) & 1) << 4);
            ldsm4(bph[0], baddr);
            ldsm4(bph[1], baddr + 16 * 80);
            ldsm4(bpl[0], baddr + ARR_B);
            ldsm4(bpl[1], baddr + ARR_B + 16 * 80);

#pragma unroll
            for (int mt = 0; mt < 4; mt++)
#pragma unroll
                for (int nt = 0; nt < 4; nt++) {
                    const uint32_t* bh = &bph[nt >> 1][(nt & 1) * 2];
                    const uint32_t* bl = &bpl[nt >> 1][(nt & 1) * 2];
                    mma_bf16(acc[mt][nt], ahi[mt], bh);
                    mma_bf16(acc[mt][nt], alo[mt], bh);
                    mma_bf16(acc[mt][nt], ahi[mt], bl);
                }
        }
        __syncthreads();
    }

    // Epilogue
#pragma unroll
    for (int mt = 0; mt < 4; mt++) {
        int r = m0 + warpm * 64 + mt * 16 + group;
#pragma unroll
        for (int nt = 0; nt < 4; nt++) {
            int col = n0 + warpn * 32 + nt * 8 + 2 * tig;
            float b0v = bias[col], b1v = bias[col + 1];
            float v0 = acc[mt][nt][0] + b0v, v1 = acc[mt][nt][1] + b1v;
            float v2 = acc[mt][nt][2] + b0v, v3 = acc[mt][nt][3] + b1v;
            if (col >= round_from) {
                v0 = __uint_as_float(to_tf32(v0));
                v1 = __uint_as_float(to_tf32(v1));
                v2 = __uint_as_float(to_tf32(v2));
                v3 = __uint_as_float(to_tf32(v3));
            }
            *(float2*)&C[(size_t)r * N + col] = make_float2(v0, v1);
            *(float2*)&C[(size_t)(r + 8) * N + col] = make_float2(v2, v3);
        }
    }
}

// ---------------------------------------------------------------------------
// RoPE (interleaved rotate_half), in place; rounds outputs to tf32 values.
// Generalized: row stride + column offset into g_QKV.
// ---------------------------------------------------------------------------
__global__ void rope_kernel(float* __restrict__ buf, const int* __restrict__ pos,
                            int nHeads, int total, int rowStride, int colOff) {
    __shared__ float sv[8][64];
    const int warp = threadIdx.x >> 5;
    const int lane = threadIdx.x & 31;
    const int vec = blockIdx.x * 8 + warp;
    if (vec >= total) return;

    const int h = vec % nHeads;
    const int bt = vec / nHeads;
    const int t = bt % TT;
    float* p = buf + (size_t)bt * rowStride + colOff + h * HD;

    sv[warp][lane] = p[lane];
    sv[warp][lane + 32] = p[lane + 32];
    __syncwarp();

    const float po = (float)pos[t];
    const float freq = exp2f(-(float)lane * (13.287712379549449f / 32.0f));
    float sn, cs;
    sincosf(po * freq, &sn, &cs);

    const int j = lane;
    const float xj = sv[warp][j];
    const float xj32 = sv[warp][j + 32];
    const float rot_lo = (j & 1) ? -sv[warp][47 + ((j + 1) >> 1)]
                                 : -sv[warp][16 + (j >> 1)];
    const float rot_hi = (j & 1) ? sv[warp][32 + ((j - 1) >> 1)]
                                 : sv[warp][j >> 1];
    p[j] = __uint_as_float(to_tf32(xj * cs + rot_lo * sn));
    p[j + 32] = __uint_as_float(to_tf32(xj32 * cs + rot_hi * sn));
}

// ---------------------------------------------------------------------------
// Flash attention, tf32 MMA. 128-query blocks, 256 threads (8 warps x 16 rows).
// Q fragments held in registers (Q already tf32-valued). smem = P + 2-stage KV
// = 104 KB -> 2 blocks/SM. Epilogue fuses bf16 hi/lo split of the output.
// ---------------------------------------------------------------------------
#define AW 68
__global__ __launch_bounds__(256, 2)
void attn_mma_kernel() {
    extern __shared__ float sm[];
    float* Ps = sm;                       // 128*68
    float* Ks = Ps + 128 * AW;            // 2 stages of 64*68
    float* Vs = Ks + 2 * 64 * AW;         // 2 stages of 64*68

    const int tid = threadIdx.x;
    const int wid = tid >> 5;
    const int lane = tid & 31;
    const int group = lane >> 2;
    const int tig = lane & 3;
    const int q0 = blockIdx.x * 128;
    const int h = blockIdx.y;
    const int b = blockIdx.z;
    const int kvh = h / REP;
    const int qbase = wid * 16;

    const float* Qg = g_QKV + (size_t)b * TT * QKVW + h * HD;
    const float* Kg = g_QKV + (size_t)b * TT * QKVW + CC + kvh * HD;
    const float* Vg = g_QKV + (size_t)b * TT * QKVW + CC + NKVD + kvh * HD;

    // Q fragments straight into registers (values already tf32-rounded)
    uint32_t qa[8][4];
    {
        const uint32_t* Qu = (const uint32_t*)Qg;
        const size_t r0 = (size_t)(q0 + qbase + group) * QKVW;
        const size_t r1 = r0 + 8 * QKVW;
#pragma unroll
        for (int ks = 0; ks < 8; ks++) {
            int c = ks * 8 + tig;
            qa[ks][0] = Qu[r0 + c];
            qa[ks][1] = Qu[r1 + c];
            qa[ks][2] = Qu[r0 + c + 4];
            qa[ks][3] = Qu[r1 + c + 4];
        }
    }

    auto issue_kv = [&](int stage, int j0) {
        float* Kd = Ks + stage * 64 * AW;
        float* Vd = Vs + stage * 64 * AW;
#pragma unroll
        for (int i = 0; i < 8; i++) {
            int cid = tid + i * 256;          // 0..2047
            int isV = cid >> 10;
            int within = cid & 1023;
            int row = within >> 4;            // 0..63
            int c = within & 15;
            const float* src = (isV ? Vg : Kg) + (size_t)(j0 + row) * QKVW + c * 4;
            float* dst = (isV ? Vd : Kd) + row * AW + c * 4;
            cp16(dst, src);
        }
        asm volatile("cp.async.commit_group;");
    };

    issue_kv(0, 0);

    float mr0 = -1e30f, mr1 = -1e30f, lr0 = 0.0f, lr1 = 0.0f;
    float o[8][4];
#pragma unroll
    for (int nt = 0; nt < 8; nt++)
#pragma unroll
        for (int c = 0; c < 4; c++) o[nt][c] = 0.0f;

    uint32_t* Pu = (uint32_t*)Ps;
    const int row0g = q0 + qbase + group;
    const int row1g = row0g + 8;
    const int jmax = q0 + 64;

    int stage = 0;
    for (int j0 = 0; j0 <= jmax; j0 += 64, stage ^= 1) {
        asm volatile("cp.async.wait_group 0;");
        __syncthreads();
        if (j0 + 64 <= jmax) issue_kv(stage ^ 1, j0 + 64);

        const uint32_t* Ku = (const uint32_t*)(Ks + stage * 64 * AW);
        const uint32_t* Vu = (const uint32_t*)(Vs + stage * 64 * AW);

        // ---- S = Q K^T ----
        float s[8][4];
#pragma unroll
        for (int nt = 0; nt < 8; nt++)
#pragma unroll
            for (int c = 0; c < 4; c++) s[nt][c] = 0.0f;

#pragma unroll
        for (int ks = 0; ks < 8; ks++) {
            const int kk = ks * 8;
#pragma unroll
            for (int nt = 0; nt < 8; nt++) {
                int key = nt * 8 + group;
                uint32_t b0 = Ku[key * AW + kk + tig];
                uint32_t b1 = Ku[key * AW + kk + tig + 4];
                mma_tf32(s[nt], qa[ks][0], qa[ks][1], qa[ks][2], qa[ks][3], b0, b1);
            }
        }

        // ---- scale + causal mask ----
        const bool diag = (j0 + 64 > q0);
#pragma unroll
        for (int nt = 0; nt < 8; nt++) {
            int colg = j0 + nt * 8 + 2 * tig;
            s[nt][0] *= 0.125f; s[nt][1] *= 0.125f;
            s[nt][2] *= 0.125f; s[nt][3] *= 0.125f;
            if (diag) {
                if (colg > row0g) s[nt][0] = -1e30f;
                if (colg + 1 > row0g) s[nt][1] = -1e30f;
                if (colg > row1g) s[nt][2] = -1e30f;
                if (colg + 1 > row1g) s[nt][3] = -1e30f;
            }
        }

        // ---- online softmax ----
        float mx0 = -1e30f, mx1 = -1e30f;
#pragma unroll
        for (int nt = 0; nt < 8; nt++) {
            mx0 = fmaxf(mx0, fmaxf(s[nt][0], s[nt][1]));
            mx1 = fmaxf(mx1, fmaxf(s[nt][2], s[nt][3]));
        }
        mx0 = fmaxf(mx0, __shfl_xor_sync(0xffffffffu, mx0, 1));
        mx0 = fmaxf(mx0, __shfl_xor_sync(0xffffffffu, mx0, 2));
        mx1 = fmaxf(mx1, __shfl_xor_sync(0xffffffffu, mx1, 1));
        mx1 = fmaxf(mx1, __shfl_xor_sync(0xffffffffu, mx1, 2));

        float mn0 = fmaxf(mr0, mx0), mn1 = fmaxf(mr1, mx1);
        float corr0 = __expf(mr0 - mn0), corr1 = __expf(mr1 - mn1);
        float sum0 = 0.0f, sum1 = 0.0f;
#pragma unroll
        for (int nt = 0; nt < 8; nt++) {
            s[nt][0] = __expf(s[nt][0] - mn0);
            s[nt][1] = __expf(s[nt][1] - mn0);
            s[nt][2] = __expf(s[nt][2] - mn1);
            s[nt][3] = __expf(s[nt][3] - mn1);
            sum0 += s[nt][0] + s[nt][1];
            sum1 += s[nt][2] + s[nt][3];
        }
        sum0 += __shfl_xor_sync(0xffffffffu, sum0, 1);
        sum0 += __shfl_xor_sync(0xffffffffu, sum0, 2);
        sum1 += __shfl_xor_sync(0xffffffffu, sum1, 1);
        sum1 += __shfl_xor_sync(0xffffffffu, sum1, 2);
        lr0 = lr0 * corr0 + sum0;
        lr1 = lr1 * corr1 + sum1;
        mr0 = mn0; mr1 = mn1;

#pragma unroll
        for (int nt = 0; nt < 8; nt++) {
            o[nt][0] *= corr0; o[nt][1] *= corr0;
            o[nt][2] *= corr1; o[nt][3] *= corr1;
        }

        // ---- store P (tf32 bits) to per-warp smem slice ----
        {
            int r0 = qbase + group;
#pragma unroll
            for (int nt = 0; nt < 8; nt++) {
                int col = nt * 8 + 2 * tig;
                Pu[r0 * AW + col] = to_tf32(s[nt][0]);
                Pu[r0 * AW + col + 1] = to_tf32(s[nt][1]);
                Pu[(r0 + 8) * AW + col] = to_tf32(s[nt][2]);
                Pu[(r0 + 8) * AW + col + 1] = to_tf32(s[nt][3]);
            }
        }
        __syncwarp();

        // ---- O += P V ----
#pragma unroll
        for (int ks = 0; ks < 8; ks++) {
            const int kk = ks * 8;
            const int r0 = qbase + group;
            uint32_t a0 = Pu[r0 * AW + kk + tig];
            uint32_t a1 = Pu[(r0 + 8) * AW + kk + tig];
            uint32_t a2 = Pu[r0 * AW + kk + tig + 4];
            uint32_t a3 = Pu[(r0 + 8) * AW + kk + tig + 4];
#pragma unroll
            for (int nt = 0; nt < 8; nt++) {
                int d = nt * 8 + group;
                uint32_t b0 = Vu[(kk + tig) * AW + d];
                uint32_t b1 = Vu[(kk + tig + 4) * AW + d];
                mma_tf32(o[nt], a0, a1, a2, a3, b0, b1);
            }
        }
    }

    // Epilogue: normalize, split to bf16 hi/lo, write directly
    {
        float inv0 = 1.0f / lr0, inv1 = 1.0f / lr1;
        size_t row0 = (size_t)(b * TT + row0g) * CC + h * HD;
        size_t row1 = row0 + 8 * CC;
#pragma unroll
        for (int nt = 0; nt < 8; nt++) {
            int col = nt * 8 + 2 * tig;
            float v0 = o[nt][0] * inv0, v1 = o[nt][1] * inv0;
            float v2 = o[nt][2] * inv1, v3 = o[nt][3] * inv1;
            __nv_bfloat16 h0, l0, h1, l1, h2, l2, h3, l3;
            split_one(v0, h0, l0); split_one(v1, h1, l1);
            split_one(v2, h2, l2); split_one(v3, h3, l3);
            *(__nv_bfloat162*)&g_ahi[row0 + col] = __nv_bfloat162(h0, h1);
            *(__nv_bfloat162*)&g_alo[row0 + col] = __nv_bfloat162(l0, l1);
            *(__nv_bfloat162*)&g_ahi[row1 + col] = __nv_bfloat162(h2, h3);
            *(__nv_bfloat162*)&g_alo[row1 + col] = __nv_bfloat162(l2, l3);
        }
    }
}

// ---------------------------------------------------------------------------
extern "C" void kernel_launch(void* const* d_in, const int* in_sizes, int n_in,
                              void* d_out, int out_size) {
    const float* x   = (const float*)d_in[0];
    const int*   pos = (const int*)d_in[1];
    const float* q_w = (const float*)d_in[2];
    const float* q_b = (const float*)d_in[3];
    const float* k_w = (const float*)d_in[4];
    const float* k_b = (const float*)d_in[5];
    const float* v_w = (const float*)d_in[6];
    const float* v_b = (const float*)d_in[7];
    const float* o_w = (const float*)d_in[8];
    const float* o_b = (const float*)d_in[9];
    float* out = (float*)d_out;

    float *QKVp, *bqkv;
    cudaGetSymbolAddress((void**)&QKVp, g_QKV);
    cudaGetSymbolAddress((void**)&bqkv, g_bqkv);
    __nv_bfloat16 *xhi, *xlo, *ahi, *alo, *wqkvh, *wqkvl, *woh, *wol;
    cudaGetSymbolAddress((void**)&xhi, g_xhi);
    cudaGetSymbolAddress((void**)&xlo, g_xlo);
    cudaGetSymbolAddress((void**)&ahi, g_ahi);
    cudaGetSymbolAddress((void**)&alo, g_alo);
    cudaGetSymbolAddress((void**)&wqkvh, g_wqkv_hi);
    cudaGetSymbolAddress((void**)&wqkvl, g_wqkv_lo);
    cudaGetSymbolAddress((void**)&woh, g_wo_hi);
    cudaGetSymbolAddress((void**)&wol, g_wo_lo);

    const int gemm_smem = 2 * STAGE_B;  // 81920
    cudaFuncSetAttribute(gemm_bf16x3, cudaFuncAttributeMaxDynamicSharedMemorySize,
                         gemm_smem);

    // Splits (weights transposed into combined [1280][768] hi/lo buffer)
    split_ew<<<(MM * CC / 2 + 255) / 256, 256>>>(x, xhi, xlo, MM * CC);
    split_T<<<dim3(CC / 32, CC / 32), dim3(32, 8)>>>(q_w, wqkvh, wqkvl, CC, CC);
    split_T<<<dim3(NKVD / 32, CC / 32), dim3(32, 8)>>>(
        k_w, wqkvh + (size_t)CC * CC, wqkvl + (size_t)CC * CC, CC, NKVD);
    split_T<<<dim3(NKVD / 32, CC / 32), dim3(32, 8)>>>(
        v_w, wqkvh + (size_t)(CC + NKVD) * CC, wqkvl + (size_t)(CC + NKVD) * CC, CC, NKVD);
    split_T<<<dim3(CC / 32, CC / 32), dim3(32, 8)>>>(o_w, woh, wol, CC, CC);
    concat_bias<<<(QKVW + 255) / 256, 256>>>(q_b, k_b, v_b);

    // Fused QKV projection (V columns >= 1024 rounded to tf32 in epilogue)
    gemm_bf16x3<<<dim3(QKVW / GBN, MM / GBM), 256, gemm_smem>>>(
        xhi, xlo, wqkvh, wqkvl, bqkv, QKVp, MM, QKVW, CC, CC + NKVD);

    // RoPE on Q and K inside g_QKV (rounds outputs to tf32 values)
    {
        int totQ = MM * NH;
        int totK = MM * NKV;
        rope_kernel<<<(totQ + 7) / 8, 256>>>(QKVp, pos, NH, totQ, QKVW, 0);
        rope_kernel<<<(totK + 7) / 8, 256>>>(QKVp, pos, NKV, totK, QKVW, CC);
    }

    // Attention (writes bf16 hi/lo split directly)
    {
        const int smem_bytes = (128 * AW + 4 * 64 * AW) * (int)sizeof(float); // 104448
        cudaFuncSetAttribute(attn_mma_kernel,
                             cudaFuncAttributeMaxDynamicSharedMemorySize, smem_bytes);
        attn_mma_kernel<<<dim3(TT / 128, NH, BB), 256, smem_bytes>>>();
    }

    // Output projection -> d_out
    gemm_bf16x3<<<dim3(CC / GBN, MM / GBM), 256, gemm_smem>>>(
        ahi, alo, woh, wol, o_b, out, MM, CC, CC, 1 << 30);
}